// round 8
// baseline (speedup 1.0000x reference)
#include <cuda_runtime.h>
#include <cuda_fp16.h>
#include <math.h>
#include <stdint.h>

// ---------------------------------------------------------------------------
// GTN: H = diag(s) * HA * (HB*HB2), union-sparse pattern, SMEM-staged SpMM.
// Round 8: CS=128 (acc[8][4]=32 regs, no spills), dummy-entry padding
// (no guards), MLP-8 batched entry loads. KC=128 double-buffered cp.async.
// Output: y[512*8] | all_Ws[3*2*5] | H[2*2048*2048]
// ---------------------------------------------------------------------------

#define NN    2048
#define NE    5
#define NC    2
#define CAP   256
#define NT    512
#define XD    512
#define WOUT  128
#define NCLS  8

#define Y_OFF  0
#define WS_OFF (NT * NCLS)
#define H_OFF  (WS_OFF + 3 * NC * NE)   // 4126 floats (8B aligned)

// spmm tiling
#define RB  128                 // H rows per CTA (16 warps x 8 rows)
#define CS  128                 // H cols per CTA (lane owns 4)
#define KC  128                 // k per chunk
#define NCH (NN / KC)           // 16 chunks
#define SPMM_SMEM (2 * KC * CS * 2)   // 65536 bytes

// ------------------------- static device scratch ---------------------------
__device__ int    g_cnt[NN];
__device__ int    g_cols[NN * CAP];          // k-sorted column indices
__device__ int2   g_pa [NC][NN * CAP];       // packed {col, HA weight bits}
__device__ float  g_hav [NC][NN * CAP];
__device__ float  g_hbv [NC][NN * CAP];
__device__ float  g_hb2v[NC][NN * CAP];
__device__ int    g_coff[NN][NCH + 1];       // per-row chunk start (absolute)
__device__ float  g_s[3][NC][NE];
__device__ float  g_rB  [NC][NN];
__device__ float  g_rB2 [NC][NN];
__device__ float  g_rM  [NC][NN];
__device__ float  g_deg0[NC][NN];
__device__ float  g_scale[NC][NN];
__device__ __align__(16) __half g_Mh[NC][NN][NN];   // M = HB@HB2, fp16
__device__ float  g_gwT[XD][WOUT];

// ------------------------------ helpers ------------------------------------
__device__ __forceinline__ uint32_t smem_u32(const void* p) {
    uint32_t a;
    asm("{ .reg .u64 t; cvta.to.shared.u64 t, %1; cvt.u32.u64 %0, t; }" : "=r"(a) : "l"(p));
    return a;
}
__device__ __forceinline__ float warpSum(float v) {
    #pragma unroll
    for (int o = 16; o > 0; o >>= 1) v += __shfl_down_sync(0xffffffffu, v, o);
    return v;
}
__device__ __forceinline__ void cp_async16(uint32_t dst, const void* src) {
    asm volatile("cp.async.cg.shared.global [%0], [%1], 16;" :: "r"(dst), "l"(src) : "memory");
}

// --------------------------- kernel 1: init --------------------------------
__global__ void k_init(const float* __restrict__ w1, const float* __restrict__ w2,
                       const float* __restrict__ w3, float* __restrict__ out_ws) {
    int tid = threadIdx.x;
    if (tid < 3 * NC) {
        int m = tid / NC, c = tid % NC;
        const float* w = (m == 0 ? w1 : (m == 1 ? w2 : w3)) + c * NE;
        float mx = w[0];
        #pragma unroll
        for (int e = 1; e < NE; e++) mx = fmaxf(mx, w[e]);
        float ex[NE], s = 0.f;
        #pragma unroll
        for (int e = 0; e < NE; e++) { ex[e] = expf(w[e] - mx); s += ex[e]; }
        float inv = 1.f / s;
        #pragma unroll
        for (int e = 0; e < NE; e++) {
            float v = ex[e] * inv;
            g_s[m][c][e] = v;
            out_ws[m * NC * NE + c * NE + e] = v;
        }
    }
}

// ---- kernel 2: build k-SORTED sparse pattern + values (block scan) --------
__global__ void k_fill(const float* __restrict__ A) {
    int i = blockIdx.x;
    int tid = threadIdx.x, lane = tid & 31, w = tid >> 5;
    __shared__ int warpoff[8];
    __shared__ int base;
    if (tid == 0) base = 0;
    float s1[NC][NE], s2[NC][NE], s3[NC][NE];
    #pragma unroll
    for (int c = 0; c < NC; c++)
        #pragma unroll
        for (int e = 0; e < NE; e++) {
            s1[c][e] = g_s[0][c][e]; s2[c][e] = g_s[1][c][e]; s3[c][e] = g_s[2][c][e];
        }
    __syncthreads();
    for (int s = 0; s < 8; s++) {
        int j = s * 256 + tid;
        float a[NE];
        bool nz = false;
        #pragma unroll
        for (int e = 0; e < NE; e++) {
            a[e] = A[(size_t)e * NN * NN + (size_t)i * NN + j];
            nz |= (a[e] != 0.f);
        }
        unsigned mask = __ballot_sync(0xffffffffu, nz);
        if (lane == 0) warpoff[w] = __popc(mask);
        __syncthreads();
        int woff = 0;
        #pragma unroll
        for (int k = 0; k < 8; k++) if (k < w) woff += warpoff[k];
        int slot = base + woff + __popc(mask & ((1u << lane) - 1u));
        if (nz && slot < CAP) {
            int p = i * CAP + slot;
            g_cols[p] = j;
            #pragma unroll
            for (int c = 0; c < NC; c++) {
                float va = 0.f, vb = 0.f, vb2 = 0.f;
                #pragma unroll
                for (int e = 0; e < NE; e++) {
                    va  += s1[c][e] * a[e];
                    vb  += s2[c][e] * a[e];
                    vb2 += s3[c][e] * a[e];
                }
                g_hav[c][p] = va; g_hbv[c][p] = vb; g_hb2v[c][p] = vb2;
                g_pa[c][p] = make_int2(j, __float_as_int(va));
            }
        }
        __syncthreads();
        if (tid == 0) {
            int tot = 0;
            #pragma unroll
            for (int k = 0; k < 8; k++) tot += warpoff[k];
            base += tot;
        }
        __syncthreads();
    }
    if (tid == 0) g_cnt[i] = min(base, CAP);
}

// ---- kernel 2b: per-row per-chunk offsets ---------------------------------
__global__ void k_coff() {
    int i = blockIdx.x;
    __shared__ int hist[NCH];
    if (threadIdx.x < NCH) hist[threadIdx.x] = 0;
    __syncthreads();
    int cnt = g_cnt[i];
    for (int t = threadIdx.x; t < cnt; t += blockDim.x)
        atomicAdd(&hist[g_cols[i * CAP + t] / KC], 1);
    __syncthreads();
    if (threadIdx.x == 0) {
        int run = i * CAP;
        #pragma unroll
        for (int k = 0; k < NCH; k++) { g_coff[i][k] = run; run += hist[k]; }
        g_coff[i][NCH] = run;
    }
}

// --------------- kernel 3: row sums of HB, HB2 -----------------------------
__global__ void k_rowstats() {
    int r = blockIdx.x;
    int cnt = min(g_cnt[r], CAP);
    float a0 = 0, a1 = 0, b0 = 0, b1 = 0;
    for (int t = threadIdx.x; t < cnt; t += blockDim.x) {
        int p = r * CAP + t;
        a0 += g_hbv[0][p];  a1 += g_hbv[1][p];
        b0 += g_hb2v[0][p]; b1 += g_hb2v[1][p];
    }
    a0 = warpSum(a0); a1 = warpSum(a1); b0 = warpSum(b0); b1 = warpSum(b1);
    __shared__ float sh[4][4];
    int w = threadIdx.x >> 5, lane = threadIdx.x & 31;
    if (lane == 0) { sh[w][0] = a0; sh[w][1] = a1; sh[w][2] = b0; sh[w][3] = b1; }
    __syncthreads();
    if (threadIdx.x == 0) {
        float v0 = 0, v1 = 0, v2 = 0, v3 = 0;
        for (int k = 0; k < 4; k++) { v0 += sh[k][0]; v1 += sh[k][1]; v2 += sh[k][2]; v3 += sh[k][3]; }
        g_rB[0][r] = v0; g_rB[1][r] = v1; g_rB2[0][r] = v2; g_rB2[1][r] = v3;
    }
}

// ---- kernel 4: deg0 + rowsum(M) -------------------------------------------
__global__ void k_deg() {
    int r = blockIdx.x;
    int cnt = min(g_cnt[r], CAP);
    float d0 = 0, d1 = 0, m0 = 0, m1 = 0;
    for (int t = threadIdx.x; t < cnt; t += blockDim.x) {
        int p = r * CAP + t;
        int col = g_cols[p];
        d0 += g_hav[0][p] * g_rB[0][col];
        d1 += g_hav[1][p] * g_rB[1][col];
        m0 += g_hbv[0][p] * g_rB2[0][col];
        m1 += g_hbv[1][p] * g_rB2[1][col];
    }
    d0 = warpSum(d0); d1 = warpSum(d1); m0 = warpSum(m0); m1 = warpSum(m1);
    __shared__ float sh[4][4];
    int w = threadIdx.x >> 5, lane = threadIdx.x & 31;
    if (lane == 0) { sh[w][0] = d0; sh[w][1] = d1; sh[w][2] = m0; sh[w][3] = m1; }
    __syncthreads();
    if (threadIdx.x == 0) {
        float v0 = 0, v1 = 0, v2 = 0, v3 = 0;
        for (int k = 0; k < 4; k++) { v0 += sh[k][0]; v1 += sh[k][1]; v2 += sh[k][2]; v3 += sh[k][3]; }
        g_deg0[0][r] = v0; g_deg0[1][r] = v1; g_rM[0][r] = v2; g_rM[1][r] = v3;
    }
}

// ---- kernel 5: final per-row scale ----------------------------------------
__global__ void k_scalek() {
    int r = blockIdx.x;
    int cnt = min(g_cnt[r], CAP);
    float t0 = 0, t1 = 0;
    for (int t = threadIdx.x; t < cnt; t += blockDim.x) {
        int p = r * CAP + t;
        int col = g_cols[p];
        t0 += g_hav[0][p] * g_rM[0][col];
        t1 += g_hav[1][p] * g_rM[1][col];
    }
    t0 = warpSum(t0); t1 = warpSum(t1);
    __shared__ float sh[4][2];
    int w = threadIdx.x >> 5, lane = threadIdx.x & 31;
    if (lane == 0) { sh[w][0] = t0; sh[w][1] = t1; }
    __syncthreads();
    if (threadIdx.x == 0) {
        float tt[2] = {0.f, 0.f};
        for (int k = 0; k < 4; k++) { tt[0] += sh[k][0]; tt[1] += sh[k][1]; }
        #pragma unroll
        for (int c = 0; c < NC; c++) {
            float dg0 = g_deg0[c][r];
            float d0 = (dg0 > 0.f) ? (1.f / sqrtf(dg0)) : 0.f;
            float dg1 = d0 * tt[c];
            float d1 = (dg1 > 0.f) ? (1.f / sqrtf(dg1)) : 0.f;
            g_scale[c][r] = d0 * d1;
        }
    }
}

// ---------- kernel 6: M = HB @ HB2 (sparse x sparse -> dense fp16) ---------
__global__ void k_M() {
    int k = blockIdx.x, c = blockIdx.y;
    __shared__ float acc[NN];
    for (int j = threadIdx.x; j < NN; j += blockDim.x) acc[j] = 0.f;
    __syncthreads();
    int cnt = min(g_cnt[k], CAP);
    int warp = threadIdx.x >> 5, lane = threadIdx.x & 31;
    for (int pi = warp; pi < cnt; pi += 8) {
        int p = k * CAP + pi;
        int l = g_cols[p];
        float hb = g_hbv[c][p];
        int cl = min(g_cnt[l], CAP);
        for (int qi = lane; qi < cl; qi += 32) {
            int q = l * CAP + qi;
            atomicAdd(&acc[g_cols[q]], hb * g_hb2v[c][q]);
        }
    }
    __syncthreads();
    __half2* mrow = reinterpret_cast<__half2*>(&g_Mh[c][k][0]);
    for (int j2 = threadIdx.x; j2 < NN / 2; j2 += blockDim.x)
        mrow[j2] = __floats2half2_rn(acc[2 * j2], acc[2 * j2 + 1]);
}

// ---------- kernel 7: SMEM-staged SpMM: H = diag(scale)*(HA @ M) -----------
// CTA: 128 rows x 128 cols; k chunks of 128 staged fp16 in SMEM, double buf.
// 16 warps x 8 rows; lane owns 4 cols; acc[8][4]=32 regs (fits 128-reg cap).
// Entry loads batched across rows (MLP=8); dummy zero-weight padding entries
// instead of guards (no branches, uniform control flow).
__global__ void __launch_bounds__(512, 1) k_spmm2(float* __restrict__ H) {
    extern __shared__ __align__(16) char dsm[];
    const uint32_t sb = smem_u32(dsm);
    const int c = blockIdx.z;
    const int rowbase = blockIdx.y * RB;
    const int colbase = blockIdx.x * CS;
    const int tid = threadIdx.x, lane = tid & 31, w = tid >> 5;

    float acc[8][4];
    #pragma unroll
    for (int r = 0; r < 8; r++)
        #pragma unroll
        for (int q = 0; q < 4; q++) acc[r][q] = 0.f;

    // chunk loader: 512 threads, KC=128 rows x 256B; 4 thr/row x 64B each
    const int lkr = tid >> 2, lof = (tid & 3) * 32;   // lof in halves
    auto load_chunk = [&](int buf, int n) {
        const int k0 = n * KC;
        uint32_t dst = sb + buf * (KC * CS * 2) + (uint32_t)lkr * (CS * 2) + lof * 2;
        const __half* src = &g_Mh[c][k0 + lkr][colbase + lof];
        #pragma unroll
        for (int q = 0; q < 4; q++)
            cp_async16(dst + q * 16, src + q * 8);
        asm volatile("cp.async.commit_group;" ::: "memory");
    };

    load_chunk(0, 0);
    for (int n = 0; n < NCH; n++) {
        if (n + 1 < NCH) {
            load_chunk((n + 1) & 1, n + 1);
            asm volatile("cp.async.wait_group 1;" ::: "memory");
        } else {
            asm volatile("cp.async.wait_group 0;" ::: "memory");
        }
        __syncthreads();
        const __half* Mb = reinterpret_cast<const __half*>(dsm + (n & 1) * (KC * CS * 2));
        const int k0 = n * KC;

        int pb[8], ne[8];
        #pragma unroll
        for (int rw = 0; rw < 8; rw++) {
            const int row = rowbase + w * 8 + rw;
            pb[rw] = g_coff[row][n];
            ne[rw] = g_coff[row][n + 1] - pb[rw];
        }
        int mx = 0;
        #pragma unroll
        for (int rw = 0; rw < 8; rw++) mx = max(mx, ne[rw]);

        for (int s = 0; s < mx; s++) {
            // batch: 8 independent broadcast LDG.64s (dummy {k0,0} when done)
            int2 e[8];
            #pragma unroll
            for (int rw = 0; rw < 8; rw++)
                e[rw] = (s < ne[rw]) ? g_pa[c][pb[rw] + s] : make_int2(k0, 0);
            #pragma unroll
            for (int rw = 0; rw < 8; rw++) {
                const float wv = __int_as_float(e[rw].y);
                const uint2 mv = *reinterpret_cast<const uint2*>(
                    Mb + (e[rw].x - k0) * CS + lane * 4);
                __half2 h0 = *reinterpret_cast<const __half2*>(&mv.x);
                __half2 h1 = *reinterpret_cast<const __half2*>(&mv.y);
                float2 f0 = __half22float2(h0);
                float2 f1 = __half22float2(h1);
                acc[rw][0] += wv * f0.x; acc[rw][1] += wv * f0.y;
                acc[rw][2] += wv * f1.x; acc[rw][3] += wv * f1.y;
            }
        }
        __syncthreads();
    }

    // epilogue: scale + store (float2 pairs, 8B-aligned at H_OFF)
    #pragma unroll
    for (int rw = 0; rw < 8; rw++) {
        const int row = rowbase + w * 8 + rw;
        const float sc = g_scale[c][row];
        float* out = &H[(size_t)c * NN * NN + (size_t)row * NN + colbase + lane * 4];
        float2 v0 = make_float2(sc * acc[rw][0], sc * acc[rw][1]);
        float2 v1 = make_float2(sc * acc[rw][2], sc * acc[rw][3]);
        reinterpret_cast<float2*>(out)[0] = v0;
        reinterpret_cast<float2*>(out)[1] = v1;
    }
}

// -------------------- kernel 8: transpose gcn_w ----------------------------
__global__ void k_transpose(const float* __restrict__ gw) {
    int idx = blockIdx.x * blockDim.x + threadIdx.x;
    if (idx < WOUT * XD) {
        int jj = idx / XD, kk = idx % XD;
        g_gwT[kk][jj] = gw[idx];
    }
}

// -------------------- kernel 9: classification head ------------------------
__global__ void k_head(const float* __restrict__ Xm, const float* __restrict__ gcn_b,
                       const float* __restrict__ lin_w, const float* __restrict__ lin_b,
                       const int* __restrict__ tx, float* __restrict__ y) {
    int t = blockIdx.x;
    int row = tx[t];
    __shared__ float xr[XD];
    __shared__ float h[WOUT];
    for (int k = threadIdx.x; k < XD; k += blockDim.x)
        xr[k] = Xm[(size_t)row * XD + k];
    __syncthreads();
    int j = threadIdx.x;
    float acc = gcn_b[j];
    #pragma unroll 8
    for (int k = 0; k < XD; k++) acc += g_gwT[k][j] * xr[k];
    h[j] = fmaxf(acc, 0.f);
    __syncthreads();
    if (j < NCLS) {
        float acc2 = lin_b[j];
        #pragma unroll 4
        for (int m = 0; m < WOUT; m++)
            acc2 += (lin_w[j * (NC * WOUT) + m] + lin_w[j * (NC * WOUT) + WOUT + m]) * h[m];
        y[t * NCLS + j] = acc2;
    }
}

// ------------------------------ launch -------------------------------------
extern "C" void kernel_launch(void* const* d_in, const int* in_sizes, int n_in,
                              void* d_out, int out_size) {
    const float* A     = (const float*)d_in[0];
    const float* X     = (const float*)d_in[1];
    const float* w01   = (const float*)d_in[2];
    const float* w02   = (const float*)d_in[3];
    const float* w11   = (const float*)d_in[4];
    const float* gcn_w = (const float*)d_in[5];
    const float* gcn_b = (const float*)d_in[6];
    const float* lin_w = (const float*)d_in[7];
    const float* lin_b = (const float*)d_in[8];
    const int*   tx    = (const int*)d_in[9];
    float* out = (float*)d_out;

    cudaFuncSetAttribute(k_spmm2, cudaFuncAttributeMaxDynamicSharedMemorySize, SPMM_SMEM);

    k_init<<<1, 32>>>(w01, w02, w11, out + WS_OFF);
    k_fill<<<NN, 256>>>(A);
    k_coff<<<NN, 128>>>();
    k_rowstats<<<NN, 128>>>();
    k_deg<<<NN, 128>>>();
    k_scalek<<<NN, 128>>>();
    k_M<<<dim3(NN, NC), 256>>>();
    k_spmm2<<<dim3(NN / CS, NN / RB, NC), 512, SPMM_SMEM>>>(out + H_OFF);
    k_transpose<<<(WOUT * XD + 255) / 256, 256>>>(gcn_w);
    k_head<<<NT, 128>>>(X, gcn_b, lin_w, lin_b, tx, out + Y_OFF);
}

// round 9
// speedup vs baseline: 1.7596x; 1.7596x over previous
#include <cuda_runtime.h>
#include <cuda_fp16.h>
#include <math.h>
#include <stdint.h>

// ---------------------------------------------------------------------------
// GTN: H = diag(s) * HA * (HB*HB2), union-sparse pattern, fp16 dense M.
// Round 9 = round-3 architecture (best: 294 us) + fusion/trim:
//  - k_fill computes softmax in-block, counts in SMEM, emits rowsums(HB,HB2)
//    (k_init and k_rowstats eliminated)
//  - k_M handles both channels per block (shared index loads)
//  - k_spmm: 8 cols/thread via uint4 (LDG.128), unroll 4
// Output: y[512*8] | all_Ws[3*2*5] | H[2*2048*2048]
// ---------------------------------------------------------------------------

#define NN    2048
#define NE    5
#define NC    2
#define CAP   256
#define NT    512
#define XD    512
#define WOUT  128
#define NCLS  8

#define Y_OFF  0
#define WS_OFF (NT * NCLS)
#define H_OFF  (WS_OFF + 3 * NC * NE)   // 4126 floats (8B aligned)

// ------------------------- static device scratch ---------------------------
__device__ int    g_cnt[NN];
__device__ int    g_cols[NN * CAP];
__device__ float  g_hav [NC][NN * CAP];
__device__ float  g_hbv [NC][NN * CAP];
__device__ float  g_hb2v[NC][NN * CAP];
__device__ float  g_rB  [NC][NN];
__device__ float  g_rB2 [NC][NN];
__device__ float  g_rM  [NC][NN];
__device__ float  g_deg0[NC][NN];
__device__ float  g_scale[NC][NN];
__device__ __align__(16) __half g_Mh[NC][NN][NN];   // M = HB@HB2, fp16
__device__ float  g_gwT[XD][WOUT];

// ------------------------------ helpers ------------------------------------
__device__ __forceinline__ float warpSum(float v) {
    #pragma unroll
    for (int o = 16; o > 0; o >>= 1) v += __shfl_down_sync(0xffffffffu, v, o);
    return v;
}

// ---- kernel 1: pattern + values + rowsums + softmax (fused) ---------------
__global__ void k_fill(const float* __restrict__ A,
                       const float* __restrict__ w1, const float* __restrict__ w2,
                       const float* __restrict__ w3, float* __restrict__ out_ws) {
    int i = blockIdx.x;
    int tid = threadIdx.x;
    __shared__ float ssm[3][NC][NE];
    __shared__ float srb[NC], srb2[NC];
    __shared__ int scnt;
    if (tid == 0) scnt = 0;
    if (tid < NC) { srb[tid] = 0.f; srb2[tid] = 0.f; }
    if (tid < 3 * NC) {                       // each of 6 threads: one softmax
        int m = tid / NC, c = tid % NC;
        const float* w = (m == 0 ? w1 : (m == 1 ? w2 : w3)) + c * NE;
        float mx = w[0];
        #pragma unroll
        for (int e = 1; e < NE; e++) mx = fmaxf(mx, w[e]);
        float ex[NE], s = 0.f;
        #pragma unroll
        for (int e = 0; e < NE; e++) { ex[e] = expf(w[e] - mx); s += ex[e]; }
        float inv = 1.f / s;
        #pragma unroll
        for (int e = 0; e < NE; e++) {
            float v = ex[e] * inv;
            ssm[m][c][e] = v;
            if (i == 0) out_ws[m * NC * NE + c * NE + e] = v;
        }
    }
    __syncthreads();
    float s1[NC][NE], s2[NC][NE], s3[NC][NE];
    #pragma unroll
    for (int c = 0; c < NC; c++)
        #pragma unroll
        for (int e = 0; e < NE; e++) {
            s1[c][e] = ssm[0][c][e]; s2[c][e] = ssm[1][c][e]; s3[c][e] = ssm[2][c][e];
        }
    for (int j = tid; j < NN; j += blockDim.x) {
        float a[NE];
        bool nz = false;
        #pragma unroll
        for (int e = 0; e < NE; e++) {
            a[e] = A[(size_t)e * NN * NN + (size_t)i * NN + j];
            nz |= (a[e] != 0.f);
        }
        if (nz) {
            int slot = atomicAdd(&scnt, 1);
            if (slot < CAP) {
                int p = i * CAP + slot;
                g_cols[p] = j;
                #pragma unroll
                for (int c = 0; c < NC; c++) {
                    float va = 0.f, vb = 0.f, vb2 = 0.f;
                    #pragma unroll
                    for (int e = 0; e < NE; e++) {
                        va  += s1[c][e] * a[e];
                        vb  += s2[c][e] * a[e];
                        vb2 += s3[c][e] * a[e];
                    }
                    g_hav[c][p] = va; g_hbv[c][p] = vb; g_hb2v[c][p] = vb2;
                    atomicAdd(&srb[c],  vb);
                    atomicAdd(&srb2[c], vb2);
                }
            }
        }
    }
    __syncthreads();
    if (tid < NC) { g_rB[tid][i] = srb[tid]; g_rB2[tid][i] = srb2[tid]; }
    if (tid == 0) g_cnt[i] = min(scnt, CAP);
}

// ---- kernel 2: deg0[i] = Sum HA[i,k]*rB[k]; rM[i] = Sum HB[i,k]*rB2[k] ----
__global__ void k_deg() {
    int r = blockIdx.x;
    int cnt = g_cnt[r];
    float d0 = 0, d1 = 0, m0 = 0, m1 = 0;
    for (int t = threadIdx.x; t < cnt; t += blockDim.x) {
        int p = r * CAP + t;
        int col = g_cols[p];
        d0 += g_hav[0][p] * g_rB[0][col];
        d1 += g_hav[1][p] * g_rB[1][col];
        m0 += g_hbv[0][p] * g_rB2[0][col];
        m1 += g_hbv[1][p] * g_rB2[1][col];
    }
    d0 = warpSum(d0); d1 = warpSum(d1); m0 = warpSum(m0); m1 = warpSum(m1);
    __shared__ float sh[4][4];
    int w = threadIdx.x >> 5, lane = threadIdx.x & 31;
    if (lane == 0) { sh[w][0] = d0; sh[w][1] = d1; sh[w][2] = m0; sh[w][3] = m1; }
    __syncthreads();
    if (threadIdx.x == 0) {
        float v0 = 0, v1 = 0, v2 = 0, v3 = 0;
        for (int k = 0; k < 4; k++) { v0 += sh[k][0]; v1 += sh[k][1]; v2 += sh[k][2]; v3 += sh[k][3]; }
        g_deg0[0][r] = v0; g_deg0[1][r] = v1; g_rM[0][r] = v2; g_rM[1][r] = v3;
    }
}

// ---- kernel 3: final per-row scale ----------------------------------------
__global__ void k_scalek() {
    int r = blockIdx.x;
    int cnt = g_cnt[r];
    float t0 = 0, t1 = 0;
    for (int t = threadIdx.x; t < cnt; t += blockDim.x) {
        int p = r * CAP + t;
        int col = g_cols[p];
        t0 += g_hav[0][p] * g_rM[0][col];
        t1 += g_hav[1][p] * g_rM[1][col];
    }
    t0 = warpSum(t0); t1 = warpSum(t1);
    __shared__ float sh[4][2];
    int w = threadIdx.x >> 5, lane = threadIdx.x & 31;
    if (lane == 0) { sh[w][0] = t0; sh[w][1] = t1; }
    __syncthreads();
    if (threadIdx.x == 0) {
        float tt[2] = {0.f, 0.f};
        for (int k = 0; k < 4; k++) { tt[0] += sh[k][0]; tt[1] += sh[k][1]; }
        #pragma unroll
        for (int c = 0; c < NC; c++) {
            float dg0 = g_deg0[c][r];
            float d0 = (dg0 > 0.f) ? (1.f / sqrtf(dg0)) : 0.f;
            float dg1 = d0 * tt[c];
            float d1 = (dg1 > 0.f) ? (1.f / sqrtf(dg1)) : 0.f;
            g_scale[c][r] = d0 * d1;
        }
    }
}

// ---- kernel 4: M = HB @ HB2, both channels per block ----------------------
__global__ void k_M() {
    int k = blockIdx.x;
    __shared__ float acc0[NN];
    __shared__ float acc1[NN];
    for (int j = threadIdx.x; j < NN; j += blockDim.x) { acc0[j] = 0.f; acc1[j] = 0.f; }
    __syncthreads();
    int cnt = g_cnt[k];
    int warp = threadIdx.x >> 5, lane = threadIdx.x & 31;
    for (int pi = warp; pi < cnt; pi += 8) {
        int p = k * CAP + pi;
        int l = g_cols[p];
        float hb0 = g_hbv[0][p];
        float hb1 = g_hbv[1][p];
        int cl = g_cnt[l];
        for (int qi = lane; qi < cl; qi += 32) {
            int q = l * CAP + qi;
            int col = g_cols[q];
            atomicAdd(&acc0[col], hb0 * g_hb2v[0][q]);
            atomicAdd(&acc1[col], hb1 * g_hb2v[1][q]);
        }
    }
    __syncthreads();
    __half2* m0 = reinterpret_cast<__half2*>(&g_Mh[0][k][0]);
    __half2* m1 = reinterpret_cast<__half2*>(&g_Mh[1][k][0]);
    for (int j2 = threadIdx.x; j2 < NN / 2; j2 += blockDim.x) {
        m0[j2] = __floats2half2_rn(acc0[2 * j2], acc0[2 * j2 + 1]);
        m1[j2] = __floats2half2_rn(acc1[2 * j2], acc1[2 * j2 + 1]);
    }
}

// ---- kernel 5: H = diag(scale) * HA @ M (pull SpMM, fp16 M) ---------------
// 256 threads; thread owns 8 cols via one uint4 (LDG.128) per nnz; unroll 4.
__global__ void __launch_bounds__(256) k_spmm(float* __restrict__ H) {
    const int i = blockIdx.x, c = blockIdx.y;
    const int tid = threadIdx.x;
    const int j0 = tid * 8;
    __shared__ int   scol[CAP];
    __shared__ float sw[CAP];
    const int cnt = g_cnt[i];
    if (tid < cnt) {
        int p = i * CAP + tid;
        scol[tid] = g_cols[p];
        sw[tid]   = g_hav[c][p];
    }
    __syncthreads();
    float a0 = 0, a1 = 0, a2 = 0, a3 = 0, a4 = 0, a5 = 0, a6 = 0, a7 = 0;
    int l = 0;
    for (; l + 4 <= cnt; l += 4) {
        uint4 m0 = *reinterpret_cast<const uint4*>(&g_Mh[c][scol[l + 0]][j0]);
        uint4 m1 = *reinterpret_cast<const uint4*>(&g_Mh[c][scol[l + 1]][j0]);
        uint4 m2 = *reinterpret_cast<const uint4*>(&g_Mh[c][scol[l + 2]][j0]);
        uint4 m3 = *reinterpret_cast<const uint4*>(&g_Mh[c][scol[l + 3]][j0]);
        float w0 = sw[l + 0], w1 = sw[l + 1], w2 = sw[l + 2], w3 = sw[l + 3];
        #define ACCUM(mv, wv) do {                                              \
            float2 f0 = __half22float2(*reinterpret_cast<const __half2*>(&mv.x)); \
            float2 f1 = __half22float2(*reinterpret_cast<const __half2*>(&mv.y)); \
            float2 f2 = __half22float2(*reinterpret_cast<const __half2*>(&mv.z)); \
            float2 f3 = __half22float2(*reinterpret_cast<const __half2*>(&mv.w)); \
            a0 += wv * f0.x; a1 += wv * f0.y; a2 += wv * f1.x; a3 += wv * f1.y;   \
            a4 += wv * f2.x; a5 += wv * f2.y; a6 += wv * f3.x; a7 += wv * f3.y;   \
        } while (0)
        ACCUM(m0, w0); ACCUM(m1, w1); ACCUM(m2, w2); ACCUM(m3, w3);
    }
    for (; l < cnt; l++) {
        uint4 m0 = *reinterpret_cast<const uint4*>(&g_Mh[c][scol[l]][j0]);
        float w0 = sw[l];
        ACCUM(m0, w0);
        #undef ACCUM
    }
    const float sc = g_scale[c][i];
    float* out = &H[(size_t)c * NN * NN + (size_t)i * NN + j0];
    float2* o2 = reinterpret_cast<float2*>(out);
    o2[0] = make_float2(sc * a0, sc * a1);
    o2[1] = make_float2(sc * a2, sc * a3);
    o2[2] = make_float2(sc * a4, sc * a5);
    o2[3] = make_float2(sc * a6, sc * a7);
}

// ---- kernel 6: transpose gcn_w --------------------------------------------
__global__ void k_transpose(const float* __restrict__ gw) {
    int idx = blockIdx.x * blockDim.x + threadIdx.x;
    if (idx < WOUT * XD) {
        int jj = idx / XD, kk = idx % XD;
        g_gwT[kk][jj] = gw[idx];
    }
}

// ---- kernel 7: classification head ----------------------------------------
__global__ void k_head(const float* __restrict__ Xm, const float* __restrict__ gcn_b,
                       const float* __restrict__ lin_w, const float* __restrict__ lin_b,
                       const int* __restrict__ tx, float* __restrict__ y) {
    int t = blockIdx.x;
    int row = tx[t];
    __shared__ float xr[XD];
    __shared__ float h[WOUT];
    for (int k = threadIdx.x; k < XD; k += blockDim.x)
        xr[k] = Xm[(size_t)row * XD + k];
    __syncthreads();
    int j = threadIdx.x;
    float acc = gcn_b[j];
    #pragma unroll 8
    for (int k = 0; k < XD; k++) acc += g_gwT[k][j] * xr[k];
    h[j] = fmaxf(acc, 0.f);
    __syncthreads();
    if (j < NCLS) {
        float acc2 = lin_b[j];
        #pragma unroll 4
        for (int m = 0; m < WOUT; m++)
            acc2 += (lin_w[j * (NC * WOUT) + m] + lin_w[j * (NC * WOUT) + WOUT + m]) * h[m];
        y[t * NCLS + j] = acc2;
    }
}

// ------------------------------ launch -------------------------------------
extern "C" void kernel_launch(void* const* d_in, const int* in_sizes, int n_in,
                              void* d_out, int out_size) {
    const float* A     = (const float*)d_in[0];
    const float* X     = (const float*)d_in[1];
    const float* w01   = (const float*)d_in[2];
    const float* w02   = (const float*)d_in[3];
    const float* w11   = (const float*)d_in[4];
    const float* gcn_w = (const float*)d_in[5];
    const float* gcn_b = (const float*)d_in[6];
    const float* lin_w = (const float*)d_in[7];
    const float* lin_b = (const float*)d_in[8];
    const int*   tx    = (const int*)d_in[9];
    float* out = (float*)d_out;

    k_fill<<<NN, 256>>>(A, w01, w02, w11, out + WS_OFF);
    k_deg<<<NN, 128>>>();
    k_scalek<<<NN, 128>>>();
    k_M<<<NN, 256>>>();
    k_spmm<<<dim3(NN, NC), 256>>>(out + H_OFF);
    k_transpose<<<(WOUT * XD + 255) / 256, 256>>>(gcn_w);
    k_head<<<NT, 128>>>(X, gcn_b, lin_w, lin_b, tx, out + Y_OFF);
}

// round 10
// speedup vs baseline: 1.9706x; 1.1199x over previous
#include <cuda_runtime.h>
#include <cuda_fp16.h>
#include <math.h>
#include <stdint.h>

// ---------------------------------------------------------------------------
// GTN: H = diag(s) * HA * (HB*HB2), union-sparse pattern, fp16 dense M.
// Round 10 = round-9 + k_M rewritten with f16x2 SIMD shared atomics:
//   both channels packed in __half2 -> per entry: 2 LDG + 1 ATOMS.F16x2
//   (was 3 LDG + 2 ATOMS.F32). Accumulator already fp16 -> cheap writeout.
// Output: y[512*8] | all_Ws[3*2*5] | H[2*2048*2048]
// ---------------------------------------------------------------------------

#define NN    2048
#define NE    5
#define NC    2
#define CAP   256
#define NT    512
#define XD    512
#define WOUT  128
#define NCLS  8

#define Y_OFF  0
#define WS_OFF (NT * NCLS)
#define H_OFF  (WS_OFF + 3 * NC * NE)   // 4126 floats (8B aligned)

// ------------------------- static device scratch ---------------------------
__device__ int     g_cnt[NN];
__device__ int     g_cols[NN * CAP];
__device__ float   g_hav [NC][NN * CAP];
__device__ float   g_hbv [NC][NN * CAP];
__device__ float   g_hb2v[NC][NN * CAP];
__device__ __half2 g_hbp [NN * CAP];         // {HB c0, HB c1} packed
__device__ __half2 g_hb2p[NN * CAP];         // {HB2 c0, HB2 c1} packed
__device__ float   g_rB  [NC][NN];
__device__ float   g_rB2 [NC][NN];
__device__ float   g_rM  [NC][NN];
__device__ float   g_deg0[NC][NN];
__device__ float   g_scale[NC][NN];
__device__ __align__(16) __half g_Mh[NC][NN][NN];   // M = HB@HB2, fp16
__device__ float   g_gwT[XD][WOUT];

// ------------------------------ helpers ------------------------------------
__device__ __forceinline__ float warpSum(float v) {
    #pragma unroll
    for (int o = 16; o > 0; o >>= 1) v += __shfl_down_sync(0xffffffffu, v, o);
    return v;
}

// ---- kernel 1: pattern + values + rowsums + softmax (fused) ---------------
__global__ void k_fill(const float* __restrict__ A,
                       const float* __restrict__ w1, const float* __restrict__ w2,
                       const float* __restrict__ w3, float* __restrict__ out_ws) {
    int i = blockIdx.x;
    int tid = threadIdx.x;
    __shared__ float ssm[3][NC][NE];
    __shared__ float srb[NC], srb2[NC];
    __shared__ int scnt;
    if (tid == 0) scnt = 0;
    if (tid < NC) { srb[tid] = 0.f; srb2[tid] = 0.f; }
    if (tid < 3 * NC) {
        int m = tid / NC, c = tid % NC;
        const float* w = (m == 0 ? w1 : (m == 1 ? w2 : w3)) + c * NE;
        float mx = w[0];
        #pragma unroll
        for (int e = 1; e < NE; e++) mx = fmaxf(mx, w[e]);
        float ex[NE], s = 0.f;
        #pragma unroll
        for (int e = 0; e < NE; e++) { ex[e] = expf(w[e] - mx); s += ex[e]; }
        float inv = 1.f / s;
        #pragma unroll
        for (int e = 0; e < NE; e++) {
            float v = ex[e] * inv;
            ssm[m][c][e] = v;
            if (i == 0) out_ws[m * NC * NE + c * NE + e] = v;
        }
    }
    __syncthreads();
    float s1[NC][NE], s2[NC][NE], s3[NC][NE];
    #pragma unroll
    for (int c = 0; c < NC; c++)
        #pragma unroll
        for (int e = 0; e < NE; e++) {
            s1[c][e] = ssm[0][c][e]; s2[c][e] = ssm[1][c][e]; s3[c][e] = ssm[2][c][e];
        }
    for (int j = tid; j < NN; j += blockDim.x) {
        float a[NE];
        bool nz = false;
        #pragma unroll
        for (int e = 0; e < NE; e++) {
            a[e] = A[(size_t)e * NN * NN + (size_t)i * NN + j];
            nz |= (a[e] != 0.f);
        }
        if (nz) {
            int slot = atomicAdd(&scnt, 1);
            if (slot < CAP) {
                int p = i * CAP + slot;
                g_cols[p] = j;
                float vb_[NC], vb2_[NC];
                #pragma unroll
                for (int c = 0; c < NC; c++) {
                    float va = 0.f, vb = 0.f, vb2 = 0.f;
                    #pragma unroll
                    for (int e = 0; e < NE; e++) {
                        va  += s1[c][e] * a[e];
                        vb  += s2[c][e] * a[e];
                        vb2 += s3[c][e] * a[e];
                    }
                    g_hav[c][p] = va; g_hbv[c][p] = vb; g_hb2v[c][p] = vb2;
                    vb_[c] = vb; vb2_[c] = vb2;
                    atomicAdd(&srb[c],  vb);
                    atomicAdd(&srb2[c], vb2);
                }
                g_hbp [p] = __floats2half2_rn(vb_[0],  vb_[1]);
                g_hb2p[p] = __floats2half2_rn(vb2_[0], vb2_[1]);
            }
        }
    }
    __syncthreads();
    if (tid < NC) { g_rB[tid][i] = srb[tid]; g_rB2[tid][i] = srb2[tid]; }
    if (tid == 0) g_cnt[i] = min(scnt, CAP);
}

// ---- kernel 2: deg0[i] = Sum HA[i,k]*rB[k]; rM[i] = Sum HB[i,k]*rB2[k] ----
__global__ void k_deg() {
    int r = blockIdx.x;
    int cnt = g_cnt[r];
    float d0 = 0, d1 = 0, m0 = 0, m1 = 0;
    for (int t = threadIdx.x; t < cnt; t += blockDim.x) {
        int p = r * CAP + t;
        int col = g_cols[p];
        d0 += g_hav[0][p] * g_rB[0][col];
        d1 += g_hav[1][p] * g_rB[1][col];
        m0 += g_hbv[0][p] * g_rB2[0][col];
        m1 += g_hbv[1][p] * g_rB2[1][col];
    }
    d0 = warpSum(d0); d1 = warpSum(d1); m0 = warpSum(m0); m1 = warpSum(m1);
    __shared__ float sh[4][4];
    int w = threadIdx.x >> 5, lane = threadIdx.x & 31;
    if (lane == 0) { sh[w][0] = d0; sh[w][1] = d1; sh[w][2] = m0; sh[w][3] = m1; }
    __syncthreads();
    if (threadIdx.x == 0) {
        float v0 = 0, v1 = 0, v2 = 0, v3 = 0;
        for (int k = 0; k < 4; k++) { v0 += sh[k][0]; v1 += sh[k][1]; v2 += sh[k][2]; v3 += sh[k][3]; }
        g_deg0[0][r] = v0; g_deg0[1][r] = v1; g_rM[0][r] = v2; g_rM[1][r] = v3;
    }
}

// ---- kernel 3: final per-row scale ----------------------------------------
__global__ void k_scalek() {
    int r = blockIdx.x;
    int cnt = g_cnt[r];
    float t0 = 0, t1 = 0;
    for (int t = threadIdx.x; t < cnt; t += blockDim.x) {
        int p = r * CAP + t;
        int col = g_cols[p];
        t0 += g_hav[0][p] * g_rM[0][col];
        t1 += g_hav[1][p] * g_rM[1][col];
    }
    t0 = warpSum(t0); t1 = warpSum(t1);
    __shared__ float sh[4][2];
    int w = threadIdx.x >> 5, lane = threadIdx.x & 31;
    if (lane == 0) { sh[w][0] = t0; sh[w][1] = t1; }
    __syncthreads();
    if (threadIdx.x == 0) {
        float tt[2] = {0.f, 0.f};
        for (int k = 0; k < 4; k++) { tt[0] += sh[k][0]; tt[1] += sh[k][1]; }
        #pragma unroll
        for (int c = 0; c < NC; c++) {
            float dg0 = g_deg0[c][r];
            float d0 = (dg0 > 0.f) ? (1.f / sqrtf(dg0)) : 0.f;
            float dg1 = d0 * tt[c];
            float d1 = (dg1 > 0.f) ? (1.f / sqrtf(dg1)) : 0.f;
            g_scale[c][r] = d0 * d1;
        }
    }
}

// ---- kernel 4: M = HB @ HB2, both channels via f16x2 SIMD atomics ---------
__global__ void k_M() {
    int k = blockIdx.x;
    __shared__ __half2 acc[NN];                       // 8 KB
    for (int j = threadIdx.x; j < NN; j += blockDim.x)
        acc[j] = __float2half2_rn(0.f);
    __syncthreads();
    int cnt = g_cnt[k];
    int warp = threadIdx.x >> 5, lane = threadIdx.x & 31;
    for (int pi = warp; pi < cnt; pi += 8) {
        int p = k * CAP + pi;
        int l = g_cols[p];
        __half2 hb = g_hbp[p];                        // broadcast
        int cl = g_cnt[l];
        for (int qi = lane; qi < cl; qi += 32) {
            int q = l * CAP + qi;
            atomicAdd(&acc[g_cols[q]], __hmul2(hb, g_hb2p[q]));
        }
    }
    __syncthreads();
    // de-interleave: channel c at g_Mh[c][k][*]
    __half2* m0 = reinterpret_cast<__half2*>(&g_Mh[0][k][0]);
    __half2* m1 = reinterpret_cast<__half2*>(&g_Mh[1][k][0]);
    for (int j2 = threadIdx.x; j2 < NN / 2; j2 += blockDim.x) {
        __half2 a = acc[2 * j2], b = acc[2 * j2 + 1];
        m0[j2] = __halves2half2(__low2half(a),  __low2half(b));
        m1[j2] = __halves2half2(__high2half(a), __high2half(b));
    }
}

// ---- kernel 5: H = diag(scale) * HA @ M (pull SpMM, fp16 M) ---------------
__global__ void __launch_bounds__(256) k_spmm(float* __restrict__ H) {
    const int i = blockIdx.x, c = blockIdx.y;
    const int tid = threadIdx.x;
    const int j0 = tid * 8;
    __shared__ int   scol[CAP];
    __shared__ float sw[CAP];
    const int cnt = g_cnt[i];
    if (tid < cnt) {
        int p = i * CAP + tid;
        scol[tid] = g_cols[p];
        sw[tid]   = g_hav[c][p];
    }
    __syncthreads();
    float a0 = 0, a1 = 0, a2 = 0, a3 = 0, a4 = 0, a5 = 0, a6 = 0, a7 = 0;
    int l = 0;
    for (; l + 4 <= cnt; l += 4) {
        uint4 m0 = *reinterpret_cast<const uint4*>(&g_Mh[c][scol[l + 0]][j0]);
        uint4 m1 = *reinterpret_cast<const uint4*>(&g_Mh[c][scol[l + 1]][j0]);
        uint4 m2 = *reinterpret_cast<const uint4*>(&g_Mh[c][scol[l + 2]][j0]);
        uint4 m3 = *reinterpret_cast<const uint4*>(&g_Mh[c][scol[l + 3]][j0]);
        float w0 = sw[l + 0], w1 = sw[l + 1], w2 = sw[l + 2], w3 = sw[l + 3];
        #define ACCUM(mv, wv) do {                                                \
            float2 f0 = __half22float2(*reinterpret_cast<const __half2*>(&mv.x)); \
            float2 f1 = __half22float2(*reinterpret_cast<const __half2*>(&mv.y)); \
            float2 f2 = __half22float2(*reinterpret_cast<const __half2*>(&mv.z)); \
            float2 f3 = __half22float2(*reinterpret_cast<const __half2*>(&mv.w)); \
            a0 += wv * f0.x; a1 += wv * f0.y; a2 += wv * f1.x; a3 += wv * f1.y;   \
            a4 += wv * f2.x; a5 += wv * f2.y; a6 += wv * f3.x; a7 += wv * f3.y;   \
        } while (0)
        ACCUM(m0, w0); ACCUM(m1, w1); ACCUM(m2, w2); ACCUM(m3, w3);
    }
    for (; l < cnt; l++) {
        uint4 m0 = *reinterpret_cast<const uint4*>(&g_Mh[c][scol[l]][j0]);
        float w0 = sw[l];
        ACCUM(m0, w0);
        #undef ACCUM
    }
    const float sc = g_scale[c][i];
    float* out = &H[(size_t)c * NN * NN + (size_t)i * NN + j0];
    float2* o2 = reinterpret_cast<float2*>(out);
    o2[0] = make_float2(sc * a0, sc * a1);
    o2[1] = make_float2(sc * a2, sc * a3);
    o2[2] = make_float2(sc * a4, sc * a5);
    o2[3] = make_float2(sc * a6, sc * a7);
}

// ---- kernel 6: transpose gcn_w --------------------------------------------
__global__ void k_transpose(const float* __restrict__ gw) {
    int idx = blockIdx.x * blockDim.x + threadIdx.x;
    if (idx < WOUT * XD) {
        int jj = idx / XD, kk = idx % XD;
        g_gwT[kk][jj] = gw[idx];
    }
}

// ---- kernel 7: classification head ----------------------------------------
__global__ void k_head(const float* __restrict__ Xm, const float* __restrict__ gcn_b,
                       const float* __restrict__ lin_w, const float* __restrict__ lin_b,
                       const int* __restrict__ tx, float* __restrict__ y) {
    int t = blockIdx.x;
    int row = tx[t];
    __shared__ float xr[XD];
    __shared__ float h[WOUT];
    for (int k = threadIdx.x; k < XD; k += blockDim.x)
        xr[k] = Xm[(size_t)row * XD + k];
    __syncthreads();
    int j = threadIdx.x;
    float acc = gcn_b[j];
    #pragma unroll 8
    for (int k = 0; k < XD; k++) acc += g_gwT[k][j] * xr[k];
    h[j] = fmaxf(acc, 0.f);
    __syncthreads();
    if (j < NCLS) {
        float acc2 = lin_b[j];
        #pragma unroll 4
        for (int m = 0; m < WOUT; m++)
            acc2 += (lin_w[j * (NC * WOUT) + m] + lin_w[j * (NC * WOUT) + WOUT + m]) * h[m];
        y[t * NCLS + j] = acc2;
    }
}

// ------------------------------ launch -------------------------------------
extern "C" void kernel_launch(void* const* d_in, const int* in_sizes, int n_in,
                              void* d_out, int out_size) {
    const float* A     = (const float*)d_in[0];
    const float* X     = (const float*)d_in[1];
    const float* w01   = (const float*)d_in[2];
    const float* w02   = (const float*)d_in[3];
    const float* w11   = (const float*)d_in[4];
    const float* gcn_w = (const float*)d_in[5];
    const float* gcn_b = (const float*)d_in[6];
    const float* lin_w = (const float*)d_in[7];
    const float* lin_b = (const float*)d_in[8];
    const int*   tx    = (const int*)d_in[9];
    float* out = (float*)d_out;

    k_fill<<<NN, 256>>>(A, w01, w02, w11, out + WS_OFF);
    k_deg<<<NN, 128>>>();
    k_scalek<<<NN, 128>>>();
    k_M<<<NN, 256>>>();
    k_spmm<<<dim3(NN, NC), 256>>>(out + H_OFF);
    k_transpose<<<(WOUT * XD + 255) / 256, 256>>>(gcn_w);
    k_head<<<NT, 128>>>(X, gcn_b, lin_w, lin_b, tx, out + Y_OFF);
}

// round 11
// speedup vs baseline: 2.0131x; 1.0215x over previous
#include <cuda_runtime.h>
#include <cuda_fp16.h>
#include <math.h>
#include <stdint.h>

// ---------------------------------------------------------------------------
// GTN: H = diag(s) * HA * (HB*HB2), union-sparse pattern, fp16 dense M.
// Round 11 = round-10 + k_M entry packing: {col, val} int2 -> 1 LDG.64 + 1
// ATOMS.F16x2 per inner entry (was 2 LDG + 1 ATOMS). Dead g_hb2v removed.
// Output: y[512*8] | all_Ws[3*2*5] | H[2*2048*2048]
// ---------------------------------------------------------------------------

#define NN    2048
#define NE    5
#define NC    2
#define CAP   256
#define NT    512
#define XD    512
#define WOUT  128
#define NCLS  8

#define Y_OFF  0
#define WS_OFF (NT * NCLS)
#define H_OFF  (WS_OFF + 3 * NC * NE)   // 4126 floats (8B aligned)

// ------------------------- static device scratch ---------------------------
__device__ int     g_cnt[NN];
__device__ int     g_cols[NN * CAP];
__device__ float   g_hav [NC][NN * CAP];
__device__ float   g_hbv [NC][NN * CAP];
__device__ int2    g_pb [NN * CAP];          // {col, HB packed half2 bits}
__device__ int2    g_pb2[NN * CAP];          // {col, HB2 packed half2 bits}
__device__ float   g_rB  [NC][NN];
__device__ float   g_rB2 [NC][NN];
__device__ float   g_rM  [NC][NN];
__device__ float   g_deg0[NC][NN];
__device__ float   g_scale[NC][NN];
__device__ __align__(16) __half g_Mh[NC][NN][NN];   // M = HB@HB2, fp16
__device__ float   g_gwT[XD][WOUT];

// ------------------------------ helpers ------------------------------------
__device__ __forceinline__ float warpSum(float v) {
    #pragma unroll
    for (int o = 16; o > 0; o >>= 1) v += __shfl_down_sync(0xffffffffu, v, o);
    return v;
}
__device__ __forceinline__ __half2 bits2h2(int b) {
    __half2 h; *reinterpret_cast<int*>(&h) = b; return h;
}

// ---- kernel 1: pattern + values + rowsums + softmax (fused) ---------------
__global__ void k_fill(const float* __restrict__ A,
                       const float* __restrict__ w1, const float* __restrict__ w2,
                       const float* __restrict__ w3, float* __restrict__ out_ws) {
    int i = blockIdx.x;
    int tid = threadIdx.x;
    __shared__ float ssm[3][NC][NE];
    __shared__ float srb[NC], srb2[NC];
    __shared__ int scnt;
    if (tid == 0) scnt = 0;
    if (tid < NC) { srb[tid] = 0.f; srb2[tid] = 0.f; }
    if (tid < 3 * NC) {
        int m = tid / NC, c = tid % NC;
        const float* w = (m == 0 ? w1 : (m == 1 ? w2 : w3)) + c * NE;
        float mx = w[0];
        #pragma unroll
        for (int e = 1; e < NE; e++) mx = fmaxf(mx, w[e]);
        float ex[NE], s = 0.f;
        #pragma unroll
        for (int e = 0; e < NE; e++) { ex[e] = expf(w[e] - mx); s += ex[e]; }
        float inv = 1.f / s;
        #pragma unroll
        for (int e = 0; e < NE; e++) {
            float v = ex[e] * inv;
            ssm[m][c][e] = v;
            if (i == 0) out_ws[m * NC * NE + c * NE + e] = v;
        }
    }
    __syncthreads();
    float s1[NC][NE], s2[NC][NE], s3[NC][NE];
    #pragma unroll
    for (int c = 0; c < NC; c++)
        #pragma unroll
        for (int e = 0; e < NE; e++) {
            s1[c][e] = ssm[0][c][e]; s2[c][e] = ssm[1][c][e]; s3[c][e] = ssm[2][c][e];
        }
    for (int j = tid; j < NN; j += blockDim.x) {
        float a[NE];
        bool nz = false;
        #pragma unroll
        for (int e = 0; e < NE; e++) {
            a[e] = A[(size_t)e * NN * NN + (size_t)i * NN + j];
            nz |= (a[e] != 0.f);
        }
        if (nz) {
            int slot = atomicAdd(&scnt, 1);
            if (slot < CAP) {
                int p = i * CAP + slot;
                g_cols[p] = j;
                float vb_[NC], vb2_[NC];
                #pragma unroll
                for (int c = 0; c < NC; c++) {
                    float va = 0.f, vb = 0.f, vb2 = 0.f;
                    #pragma unroll
                    for (int e = 0; e < NE; e++) {
                        va  += s1[c][e] * a[e];
                        vb  += s2[c][e] * a[e];
                        vb2 += s3[c][e] * a[e];
                    }
                    g_hav[c][p] = va; g_hbv[c][p] = vb;
                    vb_[c] = vb; vb2_[c] = vb2;
                    atomicAdd(&srb[c],  vb);
                    atomicAdd(&srb2[c], vb2);
                }
                __half2 hb  = __floats2half2_rn(vb_[0],  vb_[1]);
                __half2 hb2 = __floats2half2_rn(vb2_[0], vb2_[1]);
                g_pb [p] = make_int2(j, *reinterpret_cast<int*>(&hb));
                g_pb2[p] = make_int2(j, *reinterpret_cast<int*>(&hb2));
            }
        }
    }
    __syncthreads();
    if (tid < NC) { g_rB[tid][i] = srb[tid]; g_rB2[tid][i] = srb2[tid]; }
    if (tid == 0) g_cnt[i] = min(scnt, CAP);
}

// ---- kernel 2: deg0[i] = Sum HA[i,k]*rB[k]; rM[i] = Sum HB[i,k]*rB2[k] ----
__global__ void k_deg() {
    int r = blockIdx.x;
    int cnt = g_cnt[r];
    float d0 = 0, d1 = 0, m0 = 0, m1 = 0;
    for (int t = threadIdx.x; t < cnt; t += blockDim.x) {
        int p = r * CAP + t;
        int col = g_cols[p];
        d0 += g_hav[0][p] * g_rB[0][col];
        d1 += g_hav[1][p] * g_rB[1][col];
        m0 += g_hbv[0][p] * g_rB2[0][col];
        m1 += g_hbv[1][p] * g_rB2[1][col];
    }
    d0 = warpSum(d0); d1 = warpSum(d1); m0 = warpSum(m0); m1 = warpSum(m1);
    __shared__ float sh[4][4];
    int w = threadIdx.x >> 5, lane = threadIdx.x & 31;
    if (lane == 0) { sh[w][0] = d0; sh[w][1] = d1; sh[w][2] = m0; sh[w][3] = m1; }
    __syncthreads();
    if (threadIdx.x == 0) {
        float v0 = 0, v1 = 0, v2 = 0, v3 = 0;
        for (int k = 0; k < 4; k++) { v0 += sh[k][0]; v1 += sh[k][1]; v2 += sh[k][2]; v3 += sh[k][3]; }
        g_deg0[0][r] = v0; g_deg0[1][r] = v1; g_rM[0][r] = v2; g_rM[1][r] = v3;
    }
}

// ---- kernel 3: final per-row scale ----------------------------------------
__global__ void k_scalek() {
    int r = blockIdx.x;
    int cnt = g_cnt[r];
    float t0 = 0, t1 = 0;
    for (int t = threadIdx.x; t < cnt; t += blockDim.x) {
        int p = r * CAP + t;
        int col = g_cols[p];
        t0 += g_hav[0][p] * g_rM[0][col];
        t1 += g_hav[1][p] * g_rM[1][col];
    }
    t0 = warpSum(t0); t1 = warpSum(t1);
    __shared__ float sh[4][2];
    int w = threadIdx.x >> 5, lane = threadIdx.x & 31;
    if (lane == 0) { sh[w][0] = t0; sh[w][1] = t1; }
    __syncthreads();
    if (threadIdx.x == 0) {
        float tt[2] = {0.f, 0.f};
        for (int k = 0; k < 4; k++) { tt[0] += sh[k][0]; tt[1] += sh[k][1]; }
        #pragma unroll
        for (int c = 0; c < NC; c++) {
            float dg0 = g_deg0[c][r];
            float d0 = (dg0 > 0.f) ? (1.f / sqrtf(dg0)) : 0.f;
            float dg1 = d0 * tt[c];
            float d1 = (dg1 > 0.f) ? (1.f / sqrtf(dg1)) : 0.f;
            g_scale[c][r] = d0 * d1;
        }
    }
}

// ---- kernel 4: M = HB @ HB2, f16x2 SIMD atomics, packed entries -----------
__global__ void k_M() {
    int k = blockIdx.x;
    __shared__ __half2 acc[NN];                       // 8 KB
    for (int j = threadIdx.x; j < NN; j += blockDim.x)
        acc[j] = __float2half2_rn(0.f);
    __syncthreads();
    int cnt = g_cnt[k];
    int warp = threadIdx.x >> 5, lane = threadIdx.x & 31;
    for (int pi = warp; pi < cnt; pi += 8) {
        int2 pe = g_pb[k * CAP + pi];                 // {col l, HB bits} 1 LDG.64
        int l = pe.x;
        __half2 hb = bits2h2(pe.y);
        int cl = g_cnt[l];
        for (int qi = lane; qi < cl; qi += 32) {
            int2 qe = g_pb2[l * CAP + qi];            // {col, HB2 bits} 1 LDG.64
            atomicAdd(&acc[qe.x], __hmul2(hb, bits2h2(qe.y)));
        }
    }
    __syncthreads();
    // de-interleave: channel c at g_Mh[c][k][*]
    __half2* m0 = reinterpret_cast<__half2*>(&g_Mh[0][k][0]);
    __half2* m1 = reinterpret_cast<__half2*>(&g_Mh[1][k][0]);
    for (int j2 = threadIdx.x; j2 < NN / 2; j2 += blockDim.x) {
        __half2 a = acc[2 * j2], b = acc[2 * j2 + 1];
        m0[j2] = __halves2half2(__low2half(a),  __low2half(b));
        m1[j2] = __halves2half2(__high2half(a), __high2half(b));
    }
}

// ---- kernel 5: H = diag(scale) * HA @ M (pull SpMM, fp16 M) ---------------
__global__ void __launch_bounds__(256) k_spmm(float* __restrict__ H) {
    const int i = blockIdx.x, c = blockIdx.y;
    const int tid = threadIdx.x;
    const int j0 = tid * 8;
    __shared__ int   scol[CAP];
    __shared__ float sw[CAP];
    const int cnt = g_cnt[i];
    if (tid < cnt) {
        int p = i * CAP + tid;
        scol[tid] = g_cols[p];
        sw[tid]   = g_hav[c][p];
    }
    __syncthreads();
    float a0 = 0, a1 = 0, a2 = 0, a3 = 0, a4 = 0, a5 = 0, a6 = 0, a7 = 0;
    int l = 0;
    for (; l + 4 <= cnt; l += 4) {
        uint4 m0 = *reinterpret_cast<const uint4*>(&g_Mh[c][scol[l + 0]][j0]);
        uint4 m1 = *reinterpret_cast<const uint4*>(&g_Mh[c][scol[l + 1]][j0]);
        uint4 m2 = *reinterpret_cast<const uint4*>(&g_Mh[c][scol[l + 2]][j0]);
        uint4 m3 = *reinterpret_cast<const uint4*>(&g_Mh[c][scol[l + 3]][j0]);
        float w0 = sw[l + 0], w1 = sw[l + 1], w2 = sw[l + 2], w3 = sw[l + 3];
        #define ACCUM(mv, wv) do {                                                \
            float2 f0 = __half22float2(*reinterpret_cast<const __half2*>(&mv.x)); \
            float2 f1 = __half22float2(*reinterpret_cast<const __half2*>(&mv.y)); \
            float2 f2 = __half22float2(*reinterpret_cast<const __half2*>(&mv.z)); \
            float2 f3 = __half22float2(*reinterpret_cast<const __half2*>(&mv.w)); \
            a0 += wv * f0.x; a1 += wv * f0.y; a2 += wv * f1.x; a3 += wv * f1.y;   \
            a4 += wv * f2.x; a5 += wv * f2.y; a6 += wv * f3.x; a7 += wv * f3.y;   \
        } while (0)
        ACCUM(m0, w0); ACCUM(m1, w1); ACCUM(m2, w2); ACCUM(m3, w3);
    }
    for (; l < cnt; l++) {
        uint4 m0 = *reinterpret_cast<const uint4*>(&g_Mh[c][scol[l]][j0]);
        float w0 = sw[l];
        ACCUM(m0, w0);
        #undef ACCUM
    }
    const float sc = g_scale[c][i];
    float* out = &H[(size_t)c * NN * NN + (size_t)i * NN + j0];
    float2* o2 = reinterpret_cast<float2*>(out);
    o2[0] = make_float2(sc * a0, sc * a1);
    o2[1] = make_float2(sc * a2, sc * a3);
    o2[2] = make_float2(sc * a4, sc * a5);
    o2[3] = make_float2(sc * a6, sc * a7);
}

// ---- kernel 6: transpose gcn_w --------------------------------------------
__global__ void k_transpose(const float* __restrict__ gw) {
    int idx = blockIdx.x * blockDim.x + threadIdx.x;
    if (idx < WOUT * XD) {
        int jj = idx / XD, kk = idx % XD;
        g_gwT[kk][jj] = gw[idx];
    }
}

// ---- kernel 7: classification head ----------------------------------------
__global__ void k_head(const float* __restrict__ Xm, const float* __restrict__ gcn_b,
                       const float* __restrict__ lin_w, const float* __restrict__ lin_b,
                       const int* __restrict__ tx, float* __restrict__ y) {
    int t = blockIdx.x;
    int row = tx[t];
    __shared__ float xr[XD];
    __shared__ float h[WOUT];
    for (int k = threadIdx.x; k < XD; k += blockDim.x)
        xr[k] = Xm[(size_t)row * XD + k];
    __syncthreads();
    int j = threadIdx.x;
    float acc = gcn_b[j];
    #pragma unroll 8
    for (int k = 0; k < XD; k++) acc += g_gwT[k][j] * xr[k];
    h[j] = fmaxf(acc, 0.f);
    __syncthreads();
    if (j < NCLS) {
        float acc2 = lin_b[j];
        #pragma unroll 4
        for (int m = 0; m < WOUT; m++)
            acc2 += (lin_w[j * (NC * WOUT) + m] + lin_w[j * (NC * WOUT) + WOUT + m]) * h[m];
        y[t * NCLS + j] = acc2;
    }
}

// ------------------------------ launch -------------------------------------
extern "C" void kernel_launch(void* const* d_in, const int* in_sizes, int n_in,
                              void* d_out, int out_size) {
    const float* A     = (const float*)d_in[0];
    const float* X     = (const float*)d_in[1];
    const float* w01   = (const float*)d_in[2];
    const float* w02   = (const float*)d_in[3];
    const float* w11   = (const float*)d_in[4];
    const float* gcn_w = (const float*)d_in[5];
    const float* gcn_b = (const float*)d_in[6];
    const float* lin_w = (const float*)d_in[7];
    const float* lin_b = (const float*)d_in[8];
    const int*   tx    = (const int*)d_in[9];
    float* out = (float*)d_out;

    k_fill<<<NN, 256>>>(A, w01, w02, w11, out + WS_OFF);
    k_deg<<<NN, 128>>>();
    k_scalek<<<NN, 128>>>();
    k_M<<<NN, 256>>>();
    k_spmm<<<dim3(NN, NC), 256>>>(out + H_OFF);
    k_transpose<<<(WOUT * XD + 255) / 256, 256>>>(gcn_w);
    k_head<<<NT, 128>>>(X, gcn_b, lin_w, lin_b, tx, out + Y_OFF);
}

// round 12
// speedup vs baseline: 2.0477x; 1.0172x over previous
#include <cuda_runtime.h>
#include <cuda_fp16.h>
#include <math.h>
#include <stdint.h>

// ---------------------------------------------------------------------------
// GTN: H = diag(s) * HA * (HB*HB2), union-sparse pattern, fp16 dense M.
// Round 12 = round-11 + k_M inner loop pairs entries: one LDG.128 (2x int2)
// + 2 ATOMS per 2 entries (was 1 LDG.64 + 1 ATOMS per entry) -> 25% fewer
// L1TEX wavefronts. Odd rows padded with a zero entry at fill time.
// Output: y[512*8] | all_Ws[3*2*5] | H[2*2048*2048]
// ---------------------------------------------------------------------------

#define NN    2048
#define NE    5
#define NC    2
#define CAP   256
#define NT    512
#define XD    512
#define WOUT  128
#define NCLS  8

#define Y_OFF  0
#define WS_OFF (NT * NCLS)
#define H_OFF  (WS_OFF + 3 * NC * NE)   // 4126 floats (8B aligned)

// ------------------------- static device scratch ---------------------------
__device__ int     g_cnt[NN];
__device__ int     g_cols[NN * CAP];
__device__ float   g_hav [NC][NN * CAP];
__device__ float   g_hbv [NC][NN * CAP];
__device__ __align__(16) int2 g_pb [NN * CAP];   // {col, HB packed half2 bits}
__device__ __align__(16) int2 g_pb2[NN * CAP];   // {col, HB2 packed half2 bits}
__device__ float   g_rB  [NC][NN];
__device__ float   g_rB2 [NC][NN];
__device__ float   g_rM  [NC][NN];
__device__ float   g_deg0[NC][NN];
__device__ float   g_scale[NC][NN];
__device__ __align__(16) __half g_Mh[NC][NN][NN];   // M = HB@HB2, fp16
__device__ float   g_gwT[XD][WOUT];

// ------------------------------ helpers ------------------------------------
__device__ __forceinline__ float warpSum(float v) {
    #pragma unroll
    for (int o = 16; o > 0; o >>= 1) v += __shfl_down_sync(0xffffffffu, v, o);
    return v;
}
__device__ __forceinline__ __half2 bits2h2(int b) {
    __half2 h; *reinterpret_cast<int*>(&h) = b; return h;
}

// ---- kernel 1: pattern + values + rowsums + softmax (fused) ---------------
__global__ void k_fill(const float* __restrict__ A,
                       const float* __restrict__ w1, const float* __restrict__ w2,
                       const float* __restrict__ w3, float* __restrict__ out_ws) {
    int i = blockIdx.x;
    int tid = threadIdx.x;
    __shared__ float ssm[3][NC][NE];
    __shared__ float srb[NC], srb2[NC];
    __shared__ int scnt;
    if (tid == 0) scnt = 0;
    if (tid < NC) { srb[tid] = 0.f; srb2[tid] = 0.f; }
    if (tid < 3 * NC) {
        int m = tid / NC, c = tid % NC;
        const float* w = (m == 0 ? w1 : (m == 1 ? w2 : w3)) + c * NE;
        float mx = w[0];
        #pragma unroll
        for (int e = 1; e < NE; e++) mx = fmaxf(mx, w[e]);
        float ex[NE], s = 0.f;
        #pragma unroll
        for (int e = 0; e < NE; e++) { ex[e] = expf(w[e] - mx); s += ex[e]; }
        float inv = 1.f / s;
        #pragma unroll
        for (int e = 0; e < NE; e++) {
            float v = ex[e] * inv;
            ssm[m][c][e] = v;
            if (i == 0) out_ws[m * NC * NE + c * NE + e] = v;
        }
    }
    __syncthreads();
    float s1[NC][NE], s2[NC][NE], s3[NC][NE];
    #pragma unroll
    for (int c = 0; c < NC; c++)
        #pragma unroll
        for (int e = 0; e < NE; e++) {
            s1[c][e] = ssm[0][c][e]; s2[c][e] = ssm[1][c][e]; s3[c][e] = ssm[2][c][e];
        }
    for (int j = tid; j < NN; j += blockDim.x) {
        float a[NE];
        bool nz = false;
        #pragma unroll
        for (int e = 0; e < NE; e++) {
            a[e] = A[(size_t)e * NN * NN + (size_t)i * NN + j];
            nz |= (a[e] != 0.f);
        }
        if (nz) {
            int slot = atomicAdd(&scnt, 1);
            if (slot < CAP) {
                int p = i * CAP + slot;
                g_cols[p] = j;
                float vb_[NC], vb2_[NC];
                #pragma unroll
                for (int c = 0; c < NC; c++) {
                    float va = 0.f, vb = 0.f, vb2 = 0.f;
                    #pragma unroll
                    for (int e = 0; e < NE; e++) {
                        va  += s1[c][e] * a[e];
                        vb  += s2[c][e] * a[e];
                        vb2 += s3[c][e] * a[e];
                    }
                    g_hav[c][p] = va; g_hbv[c][p] = vb;
                    vb_[c] = vb; vb2_[c] = vb2;
                    atomicAdd(&srb[c],  vb);
                    atomicAdd(&srb2[c], vb2);
                }
                __half2 hb  = __floats2half2_rn(vb_[0],  vb_[1]);
                __half2 hb2 = __floats2half2_rn(vb2_[0], vb2_[1]);
                g_pb [p] = make_int2(j, *reinterpret_cast<int*>(&hb));
                g_pb2[p] = make_int2(j, *reinterpret_cast<int*>(&hb2));
            }
        }
    }
    __syncthreads();
    if (tid < NC) { g_rB[tid][i] = srb[tid]; g_rB2[tid][i] = srb2[tid]; }
    if (tid == 0) {
        int cnt = min(scnt, CAP);
        g_cnt[i] = cnt;
        // pad to even for k_M's paired LDG.128 inner loop (zero no-op entry)
        if (cnt < CAP && (cnt & 1)) g_pb2[i * CAP + cnt] = make_int2(0, 0);
    }
}

// ---- kernel 2: deg0[i] = Sum HA[i,k]*rB[k]; rM[i] = Sum HB[i,k]*rB2[k] ----
__global__ void k_deg() {
    int r = blockIdx.x;
    int cnt = g_cnt[r];
    float d0 = 0, d1 = 0, m0 = 0, m1 = 0;
    for (int t = threadIdx.x; t < cnt; t += blockDim.x) {
        int p = r * CAP + t;
        int col = g_cols[p];
        d0 += g_hav[0][p] * g_rB[0][col];
        d1 += g_hav[1][p] * g_rB[1][col];
        m0 += g_hbv[0][p] * g_rB2[0][col];
        m1 += g_hbv[1][p] * g_rB2[1][col];
    }
    d0 = warpSum(d0); d1 = warpSum(d1); m0 = warpSum(m0); m1 = warpSum(m1);
    __shared__ float sh[4][4];
    int w = threadIdx.x >> 5, lane = threadIdx.x & 31;
    if (lane == 0) { sh[w][0] = d0; sh[w][1] = d1; sh[w][2] = m0; sh[w][3] = m1; }
    __syncthreads();
    if (threadIdx.x == 0) {
        float v0 = 0, v1 = 0, v2 = 0, v3 = 0;
        for (int k = 0; k < 4; k++) { v0 += sh[k][0]; v1 += sh[k][1]; v2 += sh[k][2]; v3 += sh[k][3]; }
        g_deg0[0][r] = v0; g_deg0[1][r] = v1; g_rM[0][r] = v2; g_rM[1][r] = v3;
    }
}

// ---- kernel 3: final per-row scale ----------------------------------------
__global__ void k_scalek() {
    int r = blockIdx.x;
    int cnt = g_cnt[r];
    float t0 = 0, t1 = 0;
    for (int t = threadIdx.x; t < cnt; t += blockDim.x) {
        int p = r * CAP + t;
        int col = g_cols[p];
        t0 += g_hav[0][p] * g_rM[0][col];
        t1 += g_hav[1][p] * g_rM[1][col];
    }
    t0 = warpSum(t0); t1 = warpSum(t1);
    __shared__ float sh[4][2];
    int w = threadIdx.x >> 5, lane = threadIdx.x & 31;
    if (lane == 0) { sh[w][0] = t0; sh[w][1] = t1; }
    __syncthreads();
    if (threadIdx.x == 0) {
        float tt[2] = {0.f, 0.f};
        for (int k = 0; k < 4; k++) { tt[0] += sh[k][0]; tt[1] += sh[k][1]; }
        #pragma unroll
        for (int c = 0; c < NC; c++) {
            float dg0 = g_deg0[c][r];
            float d0 = (dg0 > 0.f) ? (1.f / sqrtf(dg0)) : 0.f;
            float dg1 = d0 * tt[c];
            float d1 = (dg1 > 0.f) ? (1.f / sqrtf(dg1)) : 0.f;
            g_scale[c][r] = d0 * d1;
        }
    }
}

// ---- kernel 4: M = HB @ HB2, f16x2 SIMD atomics, paired LDG.128 -----------
__global__ void k_M() {
    int k = blockIdx.x;
    __shared__ __half2 acc[NN];                       // 8 KB
    for (int j = threadIdx.x; j < NN; j += blockDim.x)
        acc[j] = __float2half2_rn(0.f);
    __syncthreads();
    int cnt = g_cnt[k];
    int warp = threadIdx.x >> 5, lane = threadIdx.x & 31;
    for (int pi = warp; pi < cnt; pi += 8) {
        int2 pe = g_pb[k * CAP + pi];                 // {col l, HB bits}
        int l = pe.x;
        __half2 hb = bits2h2(pe.y);
        int npairs = (g_cnt[l] + 1) >> 1;             // row padded to even
        const int4* src = reinterpret_cast<const int4*>(&g_pb2[l * CAP]);
        for (int t = lane; t < npairs; t += 32) {
            int4 qq = src[t];                         // 2 entries, 1 LDG.128
            atomicAdd(&acc[qq.x], __hmul2(hb, bits2h2(qq.y)));
            atomicAdd(&acc[qq.z], __hmul2(hb, bits2h2(qq.w)));
        }
    }
    __syncthreads();
    // de-interleave: channel c at g_Mh[c][k][*]
    __half2* m0 = reinterpret_cast<__half2*>(&g_Mh[0][k][0]);
    __half2* m1 = reinterpret_cast<__half2*>(&g_Mh[1][k][0]);
    for (int j2 = threadIdx.x; j2 < NN / 2; j2 += blockDim.x) {
        __half2 a = acc[2 * j2], b = acc[2 * j2 + 1];
        m0[j2] = __halves2half2(__low2half(a),  __low2half(b));
        m1[j2] = __halves2half2(__high2half(a), __high2half(b));
    }
}

// ---- kernel 5: H = diag(scale) * HA @ M (pull SpMM, fp16 M) ---------------
__global__ void __launch_bounds__(256) k_spmm(float* __restrict__ H) {
    const int i = blockIdx.x, c = blockIdx.y;
    const int tid = threadIdx.x;
    const int j0 = tid * 8;
    __shared__ int   scol[CAP];
    __shared__ float sw[CAP];
    const int cnt = g_cnt[i];
    if (tid < cnt) {
        int p = i * CAP + tid;
        scol[tid] = g_cols[p];
        sw[tid]   = g_hav[c][p];
    }
    __syncthreads();
    float a0 = 0, a1 = 0, a2 = 0, a3 = 0, a4 = 0, a5 = 0, a6 = 0, a7 = 0;
    int l = 0;
    for (; l + 4 <= cnt; l += 4) {
        uint4 m0 = *reinterpret_cast<const uint4*>(&g_Mh[c][scol[l + 0]][j0]);
        uint4 m1 = *reinterpret_cast<const uint4*>(&g_Mh[c][scol[l + 1]][j0]);
        uint4 m2 = *reinterpret_cast<const uint4*>(&g_Mh[c][scol[l + 2]][j0]);
        uint4 m3 = *reinterpret_cast<const uint4*>(&g_Mh[c][scol[l + 3]][j0]);
        float w0 = sw[l + 0], w1 = sw[l + 1], w2 = sw[l + 2], w3 = sw[l + 3];
        #define ACCUM(mv, wv) do {                                                \
            float2 f0 = __half22float2(*reinterpret_cast<const __half2*>(&mv.x)); \
            float2 f1 = __half22float2(*reinterpret_cast<const __half2*>(&mv.y)); \
            float2 f2 = __half22float2(*reinterpret_cast<const __half2*>(&mv.z)); \
            float2 f3 = __half22float2(*reinterpret_cast<const __half2*>(&mv.w)); \
            a0 += wv * f0.x; a1 += wv * f0.y; a2 += wv * f1.x; a3 += wv * f1.y;   \
            a4 += wv * f2.x; a5 += wv * f2.y; a6 += wv * f3.x; a7 += wv * f3.y;   \
        } while (0)
        ACCUM(m0, w0); ACCUM(m1, w1); ACCUM(m2, w2); ACCUM(m3, w3);
    }
    for (; l < cnt; l++) {
        uint4 m0 = *reinterpret_cast<const uint4*>(&g_Mh[c][scol[l]][j0]);
        float w0 = sw[l];
        ACCUM(m0, w0);
        #undef ACCUM
    }
    const float sc = g_scale[c][i];
    float* out = &H[(size_t)c * NN * NN + (size_t)i * NN + j0];
    float2* o2 = reinterpret_cast<float2*>(out);
    o2[0] = make_float2(sc * a0, sc * a1);
    o2[1] = make_float2(sc * a2, sc * a3);
    o2[2] = make_float2(sc * a4, sc * a5);
    o2[3] = make_float2(sc * a6, sc * a7);
}

// ---- kernel 6: transpose gcn_w --------------------------------------------
__global__ void k_transpose(const float* __restrict__ gw) {
    int idx = blockIdx.x * blockDim.x + threadIdx.x;
    if (idx < WOUT * XD) {
        int jj = idx / XD, kk = idx % XD;
        g_gwT[kk][jj] = gw[idx];
    }
}

// ---- kernel 7: classification head ----------------------------------------
__global__ void k_head(const float* __restrict__ Xm, const float* __restrict__ gcn_b,
                       const float* __restrict__ lin_w, const float* __restrict__ lin_b,
                       const int* __restrict__ tx, float* __restrict__ y) {
    int t = blockIdx.x;
    int row = tx[t];
    __shared__ float xr[XD];
    __shared__ float h[WOUT];
    for (int k = threadIdx.x; k < XD; k += blockDim.x)
        xr[k] = Xm[(size_t)row * XD + k];
    __syncthreads();
    int j = threadIdx.x;
    float acc = gcn_b[j];
    #pragma unroll 8
    for (int k = 0; k < XD; k++) acc += g_gwT[k][j] * xr[k];
    h[j] = fmaxf(acc, 0.f);
    __syncthreads();
    if (j < NCLS) {
        float acc2 = lin_b[j];
        #pragma unroll 4
        for (int m = 0; m < WOUT; m++)
            acc2 += (lin_w[j * (NC * WOUT) + m] + lin_w[j * (NC * WOUT) + WOUT + m]) * h[m];
        y[t * NCLS + j] = acc2;
    }
}

// ------------------------------ launch -------------------------------------
extern "C" void kernel_launch(void* const* d_in, const int* in_sizes, int n_in,
                              void* d_out, int out_size) {
    const float* A     = (const float*)d_in[0];
    const float* X     = (const float*)d_in[1];
    const float* w01   = (const float*)d_in[2];
    const float* w02   = (const float*)d_in[3];
    const float* w11   = (const float*)d_in[4];
    const float* gcn_w = (const float*)d_in[5];
    const float* gcn_b = (const float*)d_in[6];
    const float* lin_w = (const float*)d_in[7];
    const float* lin_b = (const float*)d_in[8];
    const int*   tx    = (const int*)d_in[9];
    float* out = (float*)d_out;

    k_fill<<<NN, 256>>>(A, w01, w02, w11, out + WS_OFF);
    k_deg<<<NN, 128>>>();
    k_scalek<<<NN, 128>>>();
    k_M<<<NN, 256>>>();
    k_spmm<<<dim3(NN, NC), 256>>>(out + H_OFF);
    k_transpose<<<(WOUT * XD + 255) / 256, 256>>>(gcn_w);
    k_head<<<NT, 128>>>(X, gcn_b, lin_w, lin_b, tx, out + Y_OFF);
}

// round 13
// speedup vs baseline: 2.1484x; 1.0492x over previous
#include <cuda_runtime.h>
#include <cuda_fp16.h>
#include <math.h>
#include <stdint.h>

// ---------------------------------------------------------------------------
// GTN: H = diag(s) * HA * (HB*HB2), union-sparse pattern, fp16 dense M.
// Round 13 = round-12 + channel-interleaved M (__half2 {c0,c1}):
//  - k_M writeout = straight uint4 copy of the SMEM accumulator (no shuffle)
//  - k_spmm does BOTH channels per block (grid 2048): per nnz one uint4 =
//    4 cols x 2 ch; staging/barriers/blocks halved, traffic identical.
// Output: y[512*8] | all_Ws[3*2*5] | H[2*2048*2048]
// ---------------------------------------------------------------------------

#define NN    2048
#define NE    5
#define NC    2
#define CAP   256
#define NT    512
#define XD    512
#define WOUT  128
#define NCLS  8

#define Y_OFF  0
#define WS_OFF (NT * NCLS)
#define H_OFF  (WS_OFF + 3 * NC * NE)   // 4126 floats (8B aligned)

// ------------------------- static device scratch ---------------------------
__device__ int     g_cnt[NN];
__device__ int     g_cols[NN * CAP];
__device__ float   g_hav [NC][NN * CAP];
__device__ float   g_hbv [NC][NN * CAP];
__device__ __align__(16) int2 g_pb [NN * CAP];   // {col, HB packed half2 bits}
__device__ __align__(16) int2 g_pb2[NN * CAP];   // {col, HB2 packed half2 bits}
__device__ float   g_rB  [NC][NN];
__device__ float   g_rB2 [NC][NN];
__device__ float   g_rM  [NC][NN];
__device__ float   g_deg0[NC][NN];
__device__ float   g_scale[NC][NN];
__device__ __align__(16) __half2 g_Mi[NN][NN];   // M interleaved {c0,c1}, 16.8 MB
__device__ float   g_gwT[XD][WOUT];

// ------------------------------ helpers ------------------------------------
__device__ __forceinline__ float warpSum(float v) {
    #pragma unroll
    for (int o = 16; o > 0; o >>= 1) v += __shfl_down_sync(0xffffffffu, v, o);
    return v;
}
__device__ __forceinline__ __half2 bits2h2(int b) {
    __half2 h; *reinterpret_cast<int*>(&h) = b; return h;
}

// ---- kernel 1: pattern + values + rowsums + softmax (fused) ---------------
__global__ void k_fill(const float* __restrict__ A,
                       const float* __restrict__ w1, const float* __restrict__ w2,
                       const float* __restrict__ w3, float* __restrict__ out_ws) {
    int i = blockIdx.x;
    int tid = threadIdx.x;
    __shared__ float ssm[3][NC][NE];
    __shared__ float srb[NC], srb2[NC];
    __shared__ int scnt;
    if (tid == 0) scnt = 0;
    if (tid < NC) { srb[tid] = 0.f; srb2[tid] = 0.f; }
    if (tid < 3 * NC) {
        int m = tid / NC, c = tid % NC;
        const float* w = (m == 0 ? w1 : (m == 1 ? w2 : w3)) + c * NE;
        float mx = w[0];
        #pragma unroll
        for (int e = 1; e < NE; e++) mx = fmaxf(mx, w[e]);
        float ex[NE], s = 0.f;
        #pragma unroll
        for (int e = 0; e < NE; e++) { ex[e] = expf(w[e] - mx); s += ex[e]; }
        float inv = 1.f / s;
        #pragma unroll
        for (int e = 0; e < NE; e++) {
            float v = ex[e] * inv;
            ssm[m][c][e] = v;
            if (i == 0) out_ws[m * NC * NE + c * NE + e] = v;
        }
    }
    __syncthreads();
    float s1[NC][NE], s2[NC][NE], s3[NC][NE];
    #pragma unroll
    for (int c = 0; c < NC; c++)
        #pragma unroll
        for (int e = 0; e < NE; e++) {
            s1[c][e] = ssm[0][c][e]; s2[c][e] = ssm[1][c][e]; s3[c][e] = ssm[2][c][e];
        }
    for (int j = tid; j < NN; j += blockDim.x) {
        float a[NE];
        bool nz = false;
        #pragma unroll
        for (int e = 0; e < NE; e++) {
            a[e] = A[(size_t)e * NN * NN + (size_t)i * NN + j];
            nz |= (a[e] != 0.f);
        }
        if (nz) {
            int slot = atomicAdd(&scnt, 1);
            if (slot < CAP) {
                int p = i * CAP + slot;
                g_cols[p] = j;
                float vb_[NC], vb2_[NC];
                #pragma unroll
                for (int c = 0; c < NC; c++) {
                    float va = 0.f, vb = 0.f, vb2 = 0.f;
                    #pragma unroll
                    for (int e = 0; e < NE; e++) {
                        va  += s1[c][e] * a[e];
                        vb  += s2[c][e] * a[e];
                        vb2 += s3[c][e] * a[e];
                    }
                    g_hav[c][p] = va; g_hbv[c][p] = vb;
                    vb_[c] = vb; vb2_[c] = vb2;
                    atomicAdd(&srb[c],  vb);
                    atomicAdd(&srb2[c], vb2);
                }
                __half2 hb  = __floats2half2_rn(vb_[0],  vb_[1]);
                __half2 hb2 = __floats2half2_rn(vb2_[0], vb2_[1]);
                g_pb [p] = make_int2(j, *reinterpret_cast<int*>(&hb));
                g_pb2[p] = make_int2(j, *reinterpret_cast<int*>(&hb2));
            }
        }
    }
    __syncthreads();
    if (tid < NC) { g_rB[tid][i] = srb[tid]; g_rB2[tid][i] = srb2[tid]; }
    if (tid == 0) {
        int cnt = min(scnt, CAP);
        g_cnt[i] = cnt;
        // pad to even for k_M's paired LDG.128 inner loop (zero no-op entry)
        if (cnt < CAP && (cnt & 1)) g_pb2[i * CAP + cnt] = make_int2(0, 0);
    }
}

// ---- kernel 2: deg0[i] = Sum HA[i,k]*rB[k]; rM[i] = Sum HB[i,k]*rB2[k] ----
__global__ void k_deg() {
    int r = blockIdx.x;
    int cnt = g_cnt[r];
    float d0 = 0, d1 = 0, m0 = 0, m1 = 0;
    for (int t = threadIdx.x; t < cnt; t += blockDim.x) {
        int p = r * CAP + t;
        int col = g_cols[p];
        d0 += g_hav[0][p] * g_rB[0][col];
        d1 += g_hav[1][p] * g_rB[1][col];
        m0 += g_hbv[0][p] * g_rB2[0][col];
        m1 += g_hbv[1][p] * g_rB2[1][col];
    }
    d0 = warpSum(d0); d1 = warpSum(d1); m0 = warpSum(m0); m1 = warpSum(m1);
    __shared__ float sh[4][4];
    int w = threadIdx.x >> 5, lane = threadIdx.x & 31;
    if (lane == 0) { sh[w][0] = d0; sh[w][1] = d1; sh[w][2] = m0; sh[w][3] = m1; }
    __syncthreads();
    if (threadIdx.x == 0) {
        float v0 = 0, v1 = 0, v2 = 0, v3 = 0;
        for (int k = 0; k < 4; k++) { v0 += sh[k][0]; v1 += sh[k][1]; v2 += sh[k][2]; v3 += sh[k][3]; }
        g_deg0[0][r] = v0; g_deg0[1][r] = v1; g_rM[0][r] = v2; g_rM[1][r] = v3;
    }
}

// ---- kernel 3: final per-row scale ----------------------------------------
__global__ void k_scalek() {
    int r = blockIdx.x;
    int cnt = g_cnt[r];
    float t0 = 0, t1 = 0;
    for (int t = threadIdx.x; t < cnt; t += blockDim.x) {
        int p = r * CAP + t;
        int col = g_cols[p];
        t0 += g_hav[0][p] * g_rM[0][col];
        t1 += g_hav[1][p] * g_rM[1][col];
    }
    t0 = warpSum(t0); t1 = warpSum(t1);
    __shared__ float sh[4][2];
    int w = threadIdx.x >> 5, lane = threadIdx.x & 31;
    if (lane == 0) { sh[w][0] = t0; sh[w][1] = t1; }
    __syncthreads();
    if (threadIdx.x == 0) {
        float tt[2] = {0.f, 0.f};
        for (int k = 0; k < 4; k++) { tt[0] += sh[k][0]; tt[1] += sh[k][1]; }
        #pragma unroll
        for (int c = 0; c < NC; c++) {
            float dg0 = g_deg0[c][r];
            float d0 = (dg0 > 0.f) ? (1.f / sqrtf(dg0)) : 0.f;
            float dg1 = d0 * tt[c];
            float d1 = (dg1 > 0.f) ? (1.f / sqrtf(dg1)) : 0.f;
            g_scale[c][r] = d0 * d1;
        }
    }
}

// ---- kernel 4: M = HB @ HB2, f16x2 SIMD atomics, paired LDG.128 -----------
// Accumulator layout == g_Mi layout -> writeout is a straight uint4 copy.
__global__ void k_M() {
    int k = blockIdx.x;
    __shared__ __align__(16) __half2 acc[NN];         // 8 KB, {c0,c1} per col
    for (int j = threadIdx.x; j < NN; j += blockDim.x)
        acc[j] = __float2half2_rn(0.f);
    __syncthreads();
    int cnt = g_cnt[k];
    int warp = threadIdx.x >> 5, lane = threadIdx.x & 31;
    for (int pi = warp; pi < cnt; pi += 8) {
        int2 pe = g_pb[k * CAP + pi];                 // {col l, HB bits}
        int l = pe.x;
        __half2 hb = bits2h2(pe.y);
        int npairs = (g_cnt[l] + 1) >> 1;             // row padded to even
        const int4* src = reinterpret_cast<const int4*>(&g_pb2[l * CAP]);
        for (int t = lane; t < npairs; t += 32) {
            int4 qq = src[t];                         // 2 entries, 1 LDG.128
            atomicAdd(&acc[qq.x], __hmul2(hb, bits2h2(qq.y)));
            atomicAdd(&acc[qq.z], __hmul2(hb, bits2h2(qq.w)));
        }
    }
    __syncthreads();
    uint4* dst = reinterpret_cast<uint4*>(&g_Mi[k][0]);
    const uint4* s4 = reinterpret_cast<const uint4*>(acc);
    for (int t = threadIdx.x; t < NN / 4; t += blockDim.x)
        dst[t] = s4[t];                               // 16B per store
}

// ---- kernel 5: H = diag(scale) * HA @ M, both channels per block ----------
// 512 threads; thread owns 4 cols x 2 channels; one uint4 (LDG.128) per nnz.
__global__ void __launch_bounds__(512) k_spmm(float* __restrict__ H) {
    const int i = blockIdx.x;
    const int tid = threadIdx.x;
    const int j0 = tid * 4;
    __shared__ int    scol[CAP];
    __shared__ float2 sw[CAP];
    const int cnt = g_cnt[i];
    if (tid < cnt) {
        int p = i * CAP + tid;
        scol[tid] = g_cols[p];
        sw[tid]   = make_float2(g_hav[0][p], g_hav[1][p]);
    }
    __syncthreads();
    float a00 = 0, a01 = 0, a02 = 0, a03 = 0;   // channel 0
    float a10 = 0, a11 = 0, a12 = 0, a13 = 0;   // channel 1
    #define ACCUM(mv, wv) do {                                    \
        float2 f0 = __half22float2(bits2h2((int)(mv).x));         \
        float2 f1 = __half22float2(bits2h2((int)(mv).y));         \
        float2 f2 = __half22float2(bits2h2((int)(mv).z));         \
        float2 f3 = __half22float2(bits2h2((int)(mv).w));         \
        a00 += (wv).x * f0.x; a10 += (wv).y * f0.y;               \
        a01 += (wv).x * f1.x; a11 += (wv).y * f1.y;               \
        a02 += (wv).x * f2.x; a12 += (wv).y * f2.y;               \
        a03 += (wv).x * f3.x; a13 += (wv).y * f3.y;               \
    } while (0)
    int l = 0;
    for (; l + 4 <= cnt; l += 4) {
        uint4 m0 = *reinterpret_cast<const uint4*>(&g_Mi[scol[l + 0]][j0]);
        uint4 m1 = *reinterpret_cast<const uint4*>(&g_Mi[scol[l + 1]][j0]);
        uint4 m2 = *reinterpret_cast<const uint4*>(&g_Mi[scol[l + 2]][j0]);
        uint4 m3 = *reinterpret_cast<const uint4*>(&g_Mi[scol[l + 3]][j0]);
        float2 w0 = sw[l + 0], w1 = sw[l + 1], w2 = sw[l + 2], w3 = sw[l + 3];
        ACCUM(m0, w0); ACCUM(m1, w1); ACCUM(m2, w2); ACCUM(m3, w3);
    }
    for (; l < cnt; l++) {
        uint4 m0 = *reinterpret_cast<const uint4*>(&g_Mi[scol[l]][j0]);
        float2 w0 = sw[l];
        ACCUM(m0, w0);
    }
    #undef ACCUM
    const float sc0 = g_scale[0][i];
    const float sc1 = g_scale[1][i];
    float2* o0 = reinterpret_cast<float2*>(&H[(size_t)0 * NN * NN + (size_t)i * NN + j0]);
    float2* o1 = reinterpret_cast<float2*>(&H[(size_t)1 * NN * NN + (size_t)i * NN + j0]);
    o0[0] = make_float2(sc0 * a00, sc0 * a01);
    o0[1] = make_float2(sc0 * a02, sc0 * a03);
    o1[0] = make_float2(sc1 * a10, sc1 * a11);
    o1[1] = make_float2(sc1 * a12, sc1 * a13);
}

// ---- kernel 6: transpose gcn_w --------------------------------------------
__global__ void k_transpose(const float* __restrict__ gw) {
    int idx = blockIdx.x * blockDim.x + threadIdx.x;
    if (idx < WOUT * XD) {
        int jj = idx / XD, kk = idx % XD;
        g_gwT[kk][jj] = gw[idx];
    }
}

// ---- kernel 7: classification head ----------------------------------------
__global__ void k_head(const float* __restrict__ Xm, const float* __restrict__ gcn_b,
                       const float* __restrict__ lin_w, const float* __restrict__ lin_b,
                       const int* __restrict__ tx, float* __restrict__ y) {
    int t = blockIdx.x;
    int row = tx[t];
    __shared__ float xr[XD];
    __shared__ float h[WOUT];
    for (int k = threadIdx.x; k < XD; k += blockDim.x)
        xr[k] = Xm[(size_t)row * XD + k];
    __syncthreads();
    int j = threadIdx.x;
    float acc = gcn_b[j];
    #pragma unroll 8
    for (int k = 0; k < XD; k++) acc += g_gwT[k][j] * xr[k];
    h[j] = fmaxf(acc, 0.f);
    __syncthreads();
    if (j < NCLS) {
        float acc2 = lin_b[j];
        #pragma unroll 4
        for (int m = 0; m < WOUT; m++)
            acc2 += (lin_w[j * (NC * WOUT) + m] + lin_w[j * (NC * WOUT) + WOUT + m]) * h[m];
        y[t * NCLS + j] = acc2;
    }
}

// ------------------------------ launch -------------------------------------
extern "C" void kernel_launch(void* const* d_in, const int* in_sizes, int n_in,
                              void* d_out, int out_size) {
    const float* A     = (const float*)d_in[0];
    const float* X     = (const float*)d_in[1];
    const float* w01   = (const float*)d_in[2];
    const float* w02   = (const float*)d_in[3];
    const float* w11   = (const float*)d_in[4];
    const float* gcn_w = (const float*)d_in[5];
    const float* gcn_b = (const float*)d_in[6];
    const float* lin_w = (const float*)d_in[7];
    const float* lin_b = (const float*)d_in[8];
    const int*   tx    = (const int*)d_in[9];
    float* out = (float*)d_out;

    k_fill<<<NN, 256>>>(A, w01, w02, w11, out + WS_OFF);
    k_deg<<<NN, 128>>>();
    k_scalek<<<NN, 128>>>();
    k_M<<<NN, 256>>>();
    k_spmm<<<NN, 512>>>(out + H_OFF);
    k_transpose<<<(WOUT * XD + 255) / 256, 256>>>(gcn_w);
    k_head<<<NT, 128>>>(X, gcn_b, lin_w, lin_b, tx, out + Y_OFF);
}

// round 14
// speedup vs baseline: 2.2010x; 1.0245x over previous
#include <cuda_runtime.h>
#include <cuda_fp16.h>
#include <math.h>
#include <stdint.h>

// ---------------------------------------------------------------------------
// GTN: H = diag(s) * HA * (HB*HB2), union-sparse pattern, fp16 dense M.
// Round 14 = round-13 + micro-cuts:
//  - k_fill: float4 loads per edge type (4x MLP, 1/4 loop trips)
//  - k_M: outer row descriptors preloaded to SMEM (kills dependent LDG chain)
//  - k_spmm: unroll 8 (more LDG.128 in flight)
// Output: y[512*8] | all_Ws[3*2*5] | H[2*2048*2048]
// ---------------------------------------------------------------------------

#define NN    2048
#define NE    5
#define NC    2
#define CAP   256
#define NT    512
#define XD    512
#define WOUT  128
#define NCLS  8

#define Y_OFF  0
#define WS_OFF (NT * NCLS)
#define H_OFF  (WS_OFF + 3 * NC * NE)   // 4126 floats (8B aligned)

// ------------------------- static device scratch ---------------------------
__device__ int     g_cnt[NN];
__device__ int     g_cols[NN * CAP];
__device__ float   g_hav [NC][NN * CAP];
__device__ float   g_hbv [NC][NN * CAP];
__device__ __align__(16) int2 g_pb [NN * CAP];   // {col, HB packed half2 bits}
__device__ __align__(16) int2 g_pb2[NN * CAP];   // {col, HB2 packed half2 bits}
__device__ float   g_rB  [NC][NN];
__device__ float   g_rB2 [NC][NN];
__device__ float   g_rM  [NC][NN];
__device__ float   g_deg0[NC][NN];
__device__ float   g_scale[NC][NN];
__device__ __align__(16) __half2 g_Mi[NN][NN];   // M interleaved {c0,c1}, 16.8 MB
__device__ float   g_gwT[XD][WOUT];

// ------------------------------ helpers ------------------------------------
__device__ __forceinline__ float warpSum(float v) {
    #pragma unroll
    for (int o = 16; o > 0; o >>= 1) v += __shfl_down_sync(0xffffffffu, v, o);
    return v;
}
__device__ __forceinline__ __half2 bits2h2(int b) {
    __half2 h; *reinterpret_cast<int*>(&h) = b; return h;
}

// ---- kernel 1: pattern + values + rowsums + softmax (fused, float4) -------
__global__ void k_fill(const float* __restrict__ A,
                       const float* __restrict__ w1, const float* __restrict__ w2,
                       const float* __restrict__ w3, float* __restrict__ out_ws) {
    int i = blockIdx.x;
    int tid = threadIdx.x;
    __shared__ float ssm[3][NC][NE];
    __shared__ float srb[NC], srb2[NC];
    __shared__ int scnt;
    if (tid == 0) scnt = 0;
    if (tid < NC) { srb[tid] = 0.f; srb2[tid] = 0.f; }
    if (tid < 3 * NC) {
        int m = tid / NC, c = tid % NC;
        const float* w = (m == 0 ? w1 : (m == 1 ? w2 : w3)) + c * NE;
        float mx = w[0];
        #pragma unroll
        for (int e = 1; e < NE; e++) mx = fmaxf(mx, w[e]);
        float ex[NE], s = 0.f;
        #pragma unroll
        for (int e = 0; e < NE; e++) { ex[e] = expf(w[e] - mx); s += ex[e]; }
        float inv = 1.f / s;
        #pragma unroll
        for (int e = 0; e < NE; e++) {
            float v = ex[e] * inv;
            ssm[m][c][e] = v;
            if (i == 0) out_ws[m * NC * NE + c * NE + e] = v;
        }
    }
    __syncthreads();
    float s1[NC][NE], s2[NC][NE], s3[NC][NE];
    #pragma unroll
    for (int c = 0; c < NC; c++)
        #pragma unroll
        for (int e = 0; e < NE; e++) {
            s1[c][e] = ssm[0][c][e]; s2[c][e] = ssm[1][c][e]; s3[c][e] = ssm[2][c][e];
        }
    // float4 pass: thread handles 4 consecutive cols; 2 iterations
    for (int jb = tid * 4; jb < NN; jb += blockDim.x * 4) {
        float4 av[NE];
        #pragma unroll
        for (int e = 0; e < NE; e++)
            av[e] = *reinterpret_cast<const float4*>(
                A + (size_t)e * NN * NN + (size_t)i * NN + jb);
        #pragma unroll
        for (int q = 0; q < 4; q++) {
            float a[NE];
            a[0] = q == 0 ? av[0].x : q == 1 ? av[0].y : q == 2 ? av[0].z : av[0].w;
            a[1] = q == 0 ? av[1].x : q == 1 ? av[1].y : q == 2 ? av[1].z : av[1].w;
            a[2] = q == 0 ? av[2].x : q == 1 ? av[2].y : q == 2 ? av[2].z : av[2].w;
            a[3] = q == 0 ? av[3].x : q == 1 ? av[3].y : q == 2 ? av[3].z : av[3].w;
            a[4] = q == 0 ? av[4].x : q == 1 ? av[4].y : q == 2 ? av[4].z : av[4].w;
            bool nz = (a[0] != 0.f) | (a[1] != 0.f) | (a[2] != 0.f) |
                      (a[3] != 0.f) | (a[4] != 0.f);
            if (nz) {
                int slot = atomicAdd(&scnt, 1);
                if (slot < CAP) {
                    int p = i * CAP + slot;
                    int j = jb + q;
                    g_cols[p] = j;
                    float vb_[NC], vb2_[NC];
                    #pragma unroll
                    for (int c = 0; c < NC; c++) {
                        float va = 0.f, vb = 0.f, vb2 = 0.f;
                        #pragma unroll
                        for (int e = 0; e < NE; e++) {
                            va  += s1[c][e] * a[e];
                            vb  += s2[c][e] * a[e];
                            vb2 += s3[c][e] * a[e];
                        }
                        g_hav[c][p] = va; g_hbv[c][p] = vb;
                        vb_[c] = vb; vb2_[c] = vb2;
                        atomicAdd(&srb[c],  vb);
                        atomicAdd(&srb2[c], vb2);
                    }
                    __half2 hb  = __floats2half2_rn(vb_[0],  vb_[1]);
                    __half2 hb2 = __floats2half2_rn(vb2_[0], vb2_[1]);
                    g_pb [p] = make_int2(j, *reinterpret_cast<int*>(&hb));
                    g_pb2[p] = make_int2(j, *reinterpret_cast<int*>(&hb2));
                }
            }
        }
    }
    __syncthreads();
    if (tid < NC) { g_rB[tid][i] = srb[tid]; g_rB2[tid][i] = srb2[tid]; }
    if (tid == 0) {
        int cnt = min(scnt, CAP);
        g_cnt[i] = cnt;
        // pad to even for k_M's paired LDG.128 inner loop (zero no-op entry)
        if (cnt < CAP && (cnt & 1)) g_pb2[i * CAP + cnt] = make_int2(0, 0);
    }
}

// ---- kernel 2: deg0[i] = Sum HA[i,k]*rB[k]; rM[i] = Sum HB[i,k]*rB2[k] ----
__global__ void k_deg() {
    int r = blockIdx.x;
    int cnt = g_cnt[r];
    float d0 = 0, d1 = 0, m0 = 0, m1 = 0;
    for (int t = threadIdx.x; t < cnt; t += blockDim.x) {
        int p = r * CAP + t;
        int col = g_cols[p];
        d0 += g_hav[0][p] * g_rB[0][col];
        d1 += g_hav[1][p] * g_rB[1][col];
        m0 += g_hbv[0][p] * g_rB2[0][col];
        m1 += g_hbv[1][p] * g_rB2[1][col];
    }
    d0 = warpSum(d0); d1 = warpSum(d1); m0 = warpSum(m0); m1 = warpSum(m1);
    __shared__ float sh[4][4];
    int w = threadIdx.x >> 5, lane = threadIdx.x & 31;
    if (lane == 0) { sh[w][0] = d0; sh[w][1] = d1; sh[w][2] = m0; sh[w][3] = m1; }
    __syncthreads();
    if (threadIdx.x == 0) {
        float v0 = 0, v1 = 0, v2 = 0, v3 = 0;
        for (int k = 0; k < 4; k++) { v0 += sh[k][0]; v1 += sh[k][1]; v2 += sh[k][2]; v3 += sh[k][3]; }
        g_deg0[0][r] = v0; g_deg0[1][r] = v1; g_rM[0][r] = v2; g_rM[1][r] = v3;
    }
}

// ---- kernel 3: final per-row scale ----------------------------------------
__global__ void k_scalek() {
    int r = blockIdx.x;
    int cnt = g_cnt[r];
    float t0 = 0, t1 = 0;
    for (int t = threadIdx.x; t < cnt; t += blockDim.x) {
        int p = r * CAP + t;
        int col = g_cols[p];
        t0 += g_hav[0][p] * g_rM[0][col];
        t1 += g_hav[1][p] * g_rM[1][col];
    }
    t0 = warpSum(t0); t1 = warpSum(t1);
    __shared__ float sh[4][2];
    int w = threadIdx.x >> 5, lane = threadIdx.x & 31;
    if (lane == 0) { sh[w][0] = t0; sh[w][1] = t1; }
    __syncthreads();
    if (threadIdx.x == 0) {
        float tt[2] = {0.f, 0.f};
        for (int k = 0; k < 4; k++) { tt[0] += sh[k][0]; tt[1] += sh[k][1]; }
        #pragma unroll
        for (int c = 0; c < NC; c++) {
            float dg0 = g_deg0[c][r];
            float d0 = (dg0 > 0.f) ? (1.f / sqrtf(dg0)) : 0.f;
            float dg1 = d0 * tt[c];
            float d1 = (dg1 > 0.f) ? (1.f / sqrtf(dg1)) : 0.f;
            g_scale[c][r] = d0 * d1;
        }
    }
}

// ---- kernel 4: M = HB @ HB2, f16x2 SIMD atomics, descriptors in SMEM ------
__global__ void k_M() {
    int k = blockIdx.x;
    __shared__ __align__(16) __half2 acc[NN];         // 8 KB, {c0,c1} per col
    __shared__ int  sl[CAP];                          // col l per outer entry
    __shared__ int  shb[CAP];                         // HB bits per outer entry
    __shared__ int  snp[CAP];                         // npairs(l)
    for (int j = threadIdx.x; j < NN; j += blockDim.x)
        acc[j] = __float2half2_rn(0.f);
    int cnt = g_cnt[k];
    if (threadIdx.x < cnt) {
        int2 pe = g_pb[k * CAP + threadIdx.x];
        sl[threadIdx.x]  = pe.x;
        shb[threadIdx.x] = pe.y;
        snp[threadIdx.x] = (g_cnt[pe.x] + 1) >> 1;
    }
    __syncthreads();
    int warp = threadIdx.x >> 5, lane = threadIdx.x & 31;
    for (int pi = warp; pi < cnt; pi += 8) {
        int l = sl[pi];                               // broadcast LDS
        __half2 hb = bits2h2(shb[pi]);
        int npairs = snp[pi];
        const int4* src = reinterpret_cast<const int4*>(&g_pb2[l * CAP]);
        for (int t = lane; t < npairs; t += 32) {
            int4 qq = src[t];                         // 2 entries, 1 LDG.128
            atomicAdd(&acc[qq.x], __hmul2(hb, bits2h2(qq.y)));
            atomicAdd(&acc[qq.z], __hmul2(hb, bits2h2(qq.w)));
        }
    }
    __syncthreads();
    uint4* dst = reinterpret_cast<uint4*>(&g_Mi[k][0]);
    const uint4* s4 = reinterpret_cast<const uint4*>(acc);
    for (int t = threadIdx.x; t < NN / 4; t += blockDim.x)
        dst[t] = s4[t];                               // 16B per store
}

// ---- kernel 5: H = diag(scale) * HA @ M, both channels per block ----------
// 512 threads; thread owns 4 cols x 2 channels; one uint4 (LDG.128) per nnz.
__global__ void __launch_bounds__(512) k_spmm(float* __restrict__ H) {
    const int i = blockIdx.x;
    const int tid = threadIdx.x;
    const int j0 = tid * 4;
    __shared__ int    scol[CAP];
    __shared__ float2 sw[CAP];
    const int cnt = g_cnt[i];
    if (tid < cnt) {
        int p = i * CAP + tid;
        scol[tid] = g_cols[p];
        sw[tid]   = make_float2(g_hav[0][p], g_hav[1][p]);
    }
    __syncthreads();
    float a00 = 0, a01 = 0, a02 = 0, a03 = 0;   // channel 0
    float a10 = 0, a11 = 0, a12 = 0, a13 = 0;   // channel 1
    #define ACCUM(mv, wv) do {                                    \
        float2 f0 = __half22float2(bits2h2((int)(mv).x));         \
        float2 f1 = __half22float2(bits2h2((int)(mv).y));         \
        float2 f2 = __half22float2(bits2h2((int)(mv).z));         \
        float2 f3 = __half22float2(bits2h2((int)(mv).w));         \
        a00 += (wv).x * f0.x; a10 += (wv).y * f0.y;               \
        a01 += (wv).x * f1.x; a11 += (wv).y * f1.y;               \
        a02 += (wv).x * f2.x; a12 += (wv).y * f2.y;               \
        a03 += (wv).x * f3.x; a13 += (wv).y * f3.y;               \
    } while (0)
    int l = 0;
    for (; l + 8 <= cnt; l += 8) {
        uint4 m0 = *reinterpret_cast<const uint4*>(&g_Mi[scol[l + 0]][j0]);
        uint4 m1 = *reinterpret_cast<const uint4*>(&g_Mi[scol[l + 1]][j0]);
        uint4 m2 = *reinterpret_cast<const uint4*>(&g_Mi[scol[l + 2]][j0]);
        uint4 m3 = *reinterpret_cast<const uint4*>(&g_Mi[scol[l + 3]][j0]);
        uint4 m4 = *reinterpret_cast<const uint4*>(&g_Mi[scol[l + 4]][j0]);
        uint4 m5 = *reinterpret_cast<const uint4*>(&g_Mi[scol[l + 5]][j0]);
        uint4 m6 = *reinterpret_cast<const uint4*>(&g_Mi[scol[l + 6]][j0]);
        uint4 m7 = *reinterpret_cast<const uint4*>(&g_Mi[scol[l + 7]][j0]);
        float2 w0 = sw[l + 0], w1 = sw[l + 1], w2 = sw[l + 2], w3 = sw[l + 3];
        float2 w4 = sw[l + 4], w5 = sw[l + 5], w6 = sw[l + 6], w7 = sw[l + 7];
        ACCUM(m0, w0); ACCUM(m1, w1); ACCUM(m2, w2); ACCUM(m3, w3);
        ACCUM(m4, w4); ACCUM(m5, w5); ACCUM(m6, w6); ACCUM(m7, w7);
    }
    for (; l < cnt; l++) {
        uint4 m0 = *reinterpret_cast<const uint4*>(&g_Mi[scol[l]][j0]);
        float2 w0 = sw[l];
        ACCUM(m0, w0);
    }
    #undef ACCUM
    const float sc0 = g_scale[0][i];
    const float sc1 = g_scale[1][i];
    float2* o0 = reinterpret_cast<float2*>(&H[(size_t)0 * NN * NN + (size_t)i * NN + j0]);
    float2* o1 = reinterpret_cast<float2*>(&H[(size_t)1 * NN * NN + (size_t)i * NN + j0]);
    o0[0] = make_float2(sc0 * a00, sc0 * a01);
    o0[1] = make_float2(sc0 * a02, sc0 * a03);
    o1[0] = make_float2(sc1 * a10, sc1 * a11);
    o1[1] = make_float2(sc1 * a12, sc1 * a13);
}

// ---- kernel 6: transpose gcn_w --------------------------------------------
__global__ void k_transpose(const float* __restrict__ gw) {
    int idx = blockIdx.x * blockDim.x + threadIdx.x;
    if (idx < WOUT * XD) {
        int jj = idx / XD, kk = idx % XD;
        g_gwT[kk][jj] = gw[idx];
    }
}

// ---- kernel 7: classification head ----------------------------------------
__global__ void k_head(const float* __restrict__ Xm, const float* __restrict__ gcn_b,
                       const float* __restrict__ lin_w, const float* __restrict__ lin_b,
                       const int* __restrict__ tx, float* __restrict__ y) {
    int t = blockIdx.x;
    int row = tx[t];
    __shared__ float xr[XD];
    __shared__ float h[WOUT];
    for (int k = threadIdx.x; k < XD; k += blockDim.x)
        xr[k] = Xm[(size_t)row * XD + k];
    __syncthreads();
    int j = threadIdx.x;
    float acc = gcn_b[j];
    #pragma unroll 8
    for (int k = 0; k < XD; k++) acc += g_gwT[k][j] * xr[k];
    h[j] = fmaxf(acc, 0.f);
    __syncthreads();
    if (j < NCLS) {
        float acc2 = lin_b[j];
        #pragma unroll 4
        for (int m = 0; m < WOUT; m++)
            acc2 += (lin_w[j * (NC * WOUT) + m] + lin_w[j * (NC * WOUT) + WOUT + m]) * h[m];
        y[t * NCLS + j] = acc2;
    }
}

// ------------------------------ launch -------------------------------------
extern "C" void kernel_launch(void* const* d_in, const int* in_sizes, int n_in,
                              void* d_out, int out_size) {
    const float* A     = (const float*)d_in[0];
    const float* X     = (const float*)d_in[1];
    const float* w01   = (const float*)d_in[2];
    const float* w02   = (const float*)d_in[3];
    const float* w11   = (const float*)d_in[4];
    const float* gcn_w = (const float*)d_in[5];
    const float* gcn_b = (const float*)d_in[6];
    const float* lin_w = (const float*)d_in[7];
    const float* lin_b = (const float*)d_in[8];
    const int*   tx    = (const int*)d_in[9];
    float* out = (float*)d_out;

    k_fill<<<NN, 256>>>(A, w01, w02, w11, out + WS_OFF);
    k_deg<<<NN, 128>>>();
    k_scalek<<<NN, 128>>>();
    k_M<<<NN, 256>>>();
    k_spmm<<<NN, 512>>>(out + H_OFF);
    k_transpose<<<(WOUT * XD + 255) / 256, 256>>>(gcn_w);
    k_head<<<NT, 128>>>(X, gcn_b, lin_w, lin_b, tx, out + Y_OFF);
}

// round 15
// speedup vs baseline: 2.2227x; 1.0099x over previous
#include <cuda_runtime.h>
#include <cuda_fp16.h>
#include <math.h>
#include <stdint.h>

// ---------------------------------------------------------------------------
// GTN: H = diag(s) * HA * (HB*HB2), union-sparse pattern, fp16 dense M.
// Round 15 = round-14 + kernel-count reduction:
//  - k_deg folded into k_M prologue (per-row deg0/rM reduction)
//  - k_scalek folded into k_spmm prologue (inline scale computation)
//  -> pipeline: k_fill -> k_M -> k_spmm (+ transpose/head)
// Output: y[512*8] | all_Ws[3*2*5] | H[2*2048*2048]
// ---------------------------------------------------------------------------

#define NN    2048
#define NE    5
#define NC    2
#define CAP   256
#define NT    512
#define XD    512
#define WOUT  128
#define NCLS  8

#define Y_OFF  0
#define WS_OFF (NT * NCLS)
#define H_OFF  (WS_OFF + 3 * NC * NE)   // 4126 floats (8B aligned)

// ------------------------- static device scratch ---------------------------
__device__ int     g_cnt[NN];
__device__ int     g_cols[NN * CAP];
__device__ float   g_hav [NC][NN * CAP];
__device__ float   g_hbv [NC][NN * CAP];
__device__ __align__(16) int2 g_pb [NN * CAP];   // {col, HB packed half2 bits}
__device__ __align__(16) int2 g_pb2[NN * CAP];   // {col, HB2 packed half2 bits}
__device__ float   g_rB  [NC][NN];
__device__ float   g_rB2 [NC][NN];
__device__ float   g_rM  [NC][NN];
__device__ float   g_deg0[NC][NN];
__device__ __align__(16) __half2 g_Mi[NN][NN];   // M interleaved {c0,c1}, 16.8 MB
__device__ float   g_gwT[XD][WOUT];

// ------------------------------ helpers ------------------------------------
__device__ __forceinline__ float warpSum(float v) {
    #pragma unroll
    for (int o = 16; o > 0; o >>= 1) v += __shfl_down_sync(0xffffffffu, v, o);
    return v;
}
__device__ __forceinline__ __half2 bits2h2(int b) {
    __half2 h; *reinterpret_cast<int*>(&h) = b; return h;
}

// ---- kernel 1: pattern + values + rowsums + softmax (fused, float4) -------
__global__ void k_fill(const float* __restrict__ A,
                       const float* __restrict__ w1, const float* __restrict__ w2,
                       const float* __restrict__ w3, float* __restrict__ out_ws) {
    int i = blockIdx.x;
    int tid = threadIdx.x;
    __shared__ float ssm[3][NC][NE];
    __shared__ float srb[NC], srb2[NC];
    __shared__ int scnt;
    if (tid == 0) scnt = 0;
    if (tid < NC) { srb[tid] = 0.f; srb2[tid] = 0.f; }
    if (tid < 3 * NC) {
        int m = tid / NC, c = tid % NC;
        const float* w = (m == 0 ? w1 : (m == 1 ? w2 : w3)) + c * NE;
        float mx = w[0];
        #pragma unroll
        for (int e = 1; e < NE; e++) mx = fmaxf(mx, w[e]);
        float ex[NE], s = 0.f;
        #pragma unroll
        for (int e = 0; e < NE; e++) { ex[e] = expf(w[e] - mx); s += ex[e]; }
        float inv = 1.f / s;
        #pragma unroll
        for (int e = 0; e < NE; e++) {
            float v = ex[e] * inv;
            ssm[m][c][e] = v;
            if (i == 0) out_ws[m * NC * NE + c * NE + e] = v;
        }
    }
    __syncthreads();
    float s1[NC][NE], s2[NC][NE], s3[NC][NE];
    #pragma unroll
    for (int c = 0; c < NC; c++)
        #pragma unroll
        for (int e = 0; e < NE; e++) {
            s1[c][e] = ssm[0][c][e]; s2[c][e] = ssm[1][c][e]; s3[c][e] = ssm[2][c][e];
        }
    for (int jb = tid * 4; jb < NN; jb += blockDim.x * 4) {
        float4 av[NE];
        #pragma unroll
        for (int e = 0; e < NE; e++)
            av[e] = *reinterpret_cast<const float4*>(
                A + (size_t)e * NN * NN + (size_t)i * NN + jb);
        #pragma unroll
        for (int q = 0; q < 4; q++) {
            float a[NE];
            a[0] = q == 0 ? av[0].x : q == 1 ? av[0].y : q == 2 ? av[0].z : av[0].w;
            a[1] = q == 0 ? av[1].x : q == 1 ? av[1].y : q == 2 ? av[1].z : av[1].w;
            a[2] = q == 0 ? av[2].x : q == 1 ? av[2].y : q == 2 ? av[2].z : av[2].w;
            a[3] = q == 0 ? av[3].x : q == 1 ? av[3].y : q == 2 ? av[3].z : av[3].w;
            a[4] = q == 0 ? av[4].x : q == 1 ? av[4].y : q == 2 ? av[4].z : av[4].w;
            bool nz = (a[0] != 0.f) | (a[1] != 0.f) | (a[2] != 0.f) |
                      (a[3] != 0.f) | (a[4] != 0.f);
            if (nz) {
                int slot = atomicAdd(&scnt, 1);
                if (slot < CAP) {
                    int p = i * CAP + slot;
                    int j = jb + q;
                    g_cols[p] = j;
                    float vb_[NC], vb2_[NC];
                    #pragma unroll
                    for (int c = 0; c < NC; c++) {
                        float va = 0.f, vb = 0.f, vb2 = 0.f;
                        #pragma unroll
                        for (int e = 0; e < NE; e++) {
                            va  += s1[c][e] * a[e];
                            vb  += s2[c][e] * a[e];
                            vb2 += s3[c][e] * a[e];
                        }
                        g_hav[c][p] = va; g_hbv[c][p] = vb;
                        vb_[c] = vb; vb2_[c] = vb2;
                        atomicAdd(&srb[c],  vb);
                        atomicAdd(&srb2[c], vb2);
                    }
                    __half2 hb  = __floats2half2_rn(vb_[0],  vb_[1]);
                    __half2 hb2 = __floats2half2_rn(vb2_[0], vb2_[1]);
                    g_pb [p] = make_int2(j, *reinterpret_cast<int*>(&hb));
                    g_pb2[p] = make_int2(j, *reinterpret_cast<int*>(&hb2));
                }
            }
        }
    }
    __syncthreads();
    if (tid < NC) { g_rB[tid][i] = srb[tid]; g_rB2[tid][i] = srb2[tid]; }
    if (tid == 0) {
        int cnt = min(scnt, CAP);
        g_cnt[i] = cnt;
        // pad to even for k_M's paired LDG.128 inner loop (zero no-op entry)
        if (cnt < CAP && (cnt & 1)) g_pb2[i * CAP + cnt] = make_int2(0, 0);
    }
}

// ---- kernel 2: M = HB @ HB2 + per-row deg0/rM (k_deg folded in) -----------
__global__ void k_M() {
    int k = blockIdx.x;
    __shared__ __align__(16) __half2 acc[NN];         // 8 KB, {c0,c1} per col
    __shared__ int  sl[CAP];                          // col l per outer entry
    __shared__ int  shb[CAP];                         // HB bits per outer entry
    __shared__ int  snp[CAP];                         // npairs(l)
    __shared__ float sred[8][4];
    for (int j = threadIdx.x; j < NN; j += blockDim.x)
        acc[j] = __float2half2_rn(0.f);
    int cnt = g_cnt[k];
    int tid = threadIdx.x;
    // prologue: stage descriptors + per-row deg0/rM partials (k_deg fold)
    float d0 = 0.f, d1 = 0.f, m0 = 0.f, m1 = 0.f;
    if (tid < cnt) {
        int p = k * CAP + tid;
        int2 pe = g_pb[p];
        sl[tid]  = pe.x;
        shb[tid] = pe.y;
        snp[tid] = (g_cnt[pe.x] + 1) >> 1;
        int col = pe.x;
        d0 = g_hav[0][p] * g_rB[0][col];
        d1 = g_hav[1][p] * g_rB[1][col];
        m0 = g_hbv[0][p] * g_rB2[0][col];
        m1 = g_hbv[1][p] * g_rB2[1][col];
    }
    d0 = warpSum(d0); d1 = warpSum(d1); m0 = warpSum(m0); m1 = warpSum(m1);
    int warp = tid >> 5, lane = tid & 31;
    if (lane == 0) { sred[warp][0] = d0; sred[warp][1] = d1; sred[warp][2] = m0; sred[warp][3] = m1; }
    __syncthreads();
    if (tid == 0) {
        float v0 = 0, v1 = 0, v2 = 0, v3 = 0;
        #pragma unroll
        for (int q = 0; q < 8; q++) { v0 += sred[q][0]; v1 += sred[q][1]; v2 += sred[q][2]; v3 += sred[q][3]; }
        g_deg0[0][k] = v0; g_deg0[1][k] = v1; g_rM[0][k] = v2; g_rM[1][k] = v3;
    }
    // mainloop: scatter M row
    for (int pi = warp; pi < cnt; pi += 8) {
        int l = sl[pi];
        __half2 hb = bits2h2(shb[pi]);
        int npairs = snp[pi];
        const int4* src = reinterpret_cast<const int4*>(&g_pb2[l * CAP]);
        for (int t = lane; t < npairs; t += 32) {
            int4 qq = src[t];                         // 2 entries, 1 LDG.128
            atomicAdd(&acc[qq.x], __hmul2(hb, bits2h2(qq.y)));
            atomicAdd(&acc[qq.z], __hmul2(hb, bits2h2(qq.w)));
        }
    }
    __syncthreads();
    uint4* dst = reinterpret_cast<uint4*>(&g_Mi[k][0]);
    const uint4* s4 = reinterpret_cast<const uint4*>(acc);
    for (int t = threadIdx.x; t < NN / 4; t += blockDim.x)
        dst[t] = s4[t];                               // 16B per store
}

// ---- kernel 3: H = diag(scale)*HA@M, scale computed inline (k_scalek fold)
// 512 threads; thread owns 4 cols x 2 channels; one uint4 (LDG.128) per nnz.
__global__ void __launch_bounds__(512) k_spmm(float* __restrict__ H) {
    const int i = blockIdx.x;
    const int tid = threadIdx.x;
    const int j0 = tid * 4;
    __shared__ int    scol[CAP];
    __shared__ float2 sw[CAP];
    __shared__ float sred[16][2];
    __shared__ float ssc[2];
    const int cnt = g_cnt[i];
    float t0 = 0.f, t1 = 0.f;
    if (tid < cnt) {
        int p = i * CAP + tid;
        int col = g_cols[p];
        float2 wv = make_float2(g_hav[0][p], g_hav[1][p]);
        scol[tid] = col;
        sw[tid]   = wv;
        t0 = wv.x * g_rM[0][col];
        t1 = wv.y * g_rM[1][col];
    }
    t0 = warpSum(t0); t1 = warpSum(t1);
    const int warp = tid >> 5, lane = tid & 31;
    if (lane == 0) { sred[warp][0] = t0; sred[warp][1] = t1; }
    __syncthreads();
    if (tid == 0) {
        float tt0 = 0, tt1 = 0;
        #pragma unroll
        for (int q = 0; q < 16; q++) { tt0 += sred[q][0]; tt1 += sred[q][1]; }
        float dg0 = g_deg0[0][i];
        float d0 = (dg0 > 0.f) ? (1.f / sqrtf(dg0)) : 0.f;
        float dg1 = d0 * tt0;
        float d1 = (dg1 > 0.f) ? (1.f / sqrtf(dg1)) : 0.f;
        ssc[0] = d0 * d1;
        dg0 = g_deg0[1][i];
        d0 = (dg0 > 0.f) ? (1.f / sqrtf(dg0)) : 0.f;
        dg1 = d0 * tt1;
        d1 = (dg1 > 0.f) ? (1.f / sqrtf(dg1)) : 0.f;
        ssc[1] = d0 * d1;
    }
    __syncthreads();
    float a00 = 0, a01 = 0, a02 = 0, a03 = 0;   // channel 0
    float a10 = 0, a11 = 0, a12 = 0, a13 = 0;   // channel 1
    #define ACCUM(mv, wv) do {                                    \
        float2 f0 = __half22float2(bits2h2((int)(mv).x));         \
        float2 f1 = __half22float2(bits2h2((int)(mv).y));         \
        float2 f2 = __half22float2(bits2h2((int)(mv).z));         \
        float2 f3 = __half22float2(bits2h2((int)(mv).w));         \
        a00 += (wv).x * f0.x; a10 += (wv).y * f0.y;               \
        a01 += (wv).x * f1.x; a11 += (wv).y * f1.y;               \
        a02 += (wv).x * f2.x; a12 += (wv).y * f2.y;               \
        a03 += (wv).x * f3.x; a13 += (wv).y * f3.y;               \
    } while (0)
    int l = 0;
    for (; l + 8 <= cnt; l += 8) {
        uint4 m0 = *reinterpret_cast<const uint4*>(&g_Mi[scol[l + 0]][j0]);
        uint4 m1 = *reinterpret_cast<const uint4*>(&g_Mi[scol[l + 1]][j0]);
        uint4 m2 = *reinterpret_cast<const uint4*>(&g_Mi[scol[l + 2]][j0]);
        uint4 m3 = *reinterpret_cast<const uint4*>(&g_Mi[scol[l + 3]][j0]);
        uint4 m4 = *reinterpret_cast<const uint4*>(&g_Mi[scol[l + 4]][j0]);
        uint4 m5 = *reinterpret_cast<const uint4*>(&g_Mi[scol[l + 5]][j0]);
        uint4 m6 = *reinterpret_cast<const uint4*>(&g_Mi[scol[l + 6]][j0]);
        uint4 m7 = *reinterpret_cast<const uint4*>(&g_Mi[scol[l + 7]][j0]);
        float2 w0 = sw[l + 0], w1 = sw[l + 1], w2 = sw[l + 2], w3 = sw[l + 3];
        float2 w4 = sw[l + 4], w5 = sw[l + 5], w6 = sw[l + 6], w7 = sw[l + 7];
        ACCUM(m0, w0); ACCUM(m1, w1); ACCUM(m2, w2); ACCUM(m3, w3);
        ACCUM(m4, w4); ACCUM(m5, w5); ACCUM(m6, w6); ACCUM(m7, w7);
    }
    for (; l < cnt; l++) {
        uint4 m0 = *reinterpret_cast<const uint4*>(&g_Mi[scol[l]][j0]);
        float2 w0 = sw[l];
        ACCUM(m0, w0);
    }
    #undef ACCUM
    const float sc0 = ssc[0];
    const float sc1 = ssc[1];
    float2* o0 = reinterpret_cast<float2*>(&H[(size_t)0 * NN * NN + (size_t)i * NN + j0]);
    float2* o1 = reinterpret_cast<float2*>(&H[(size_t)1 * NN * NN + (size_t)i * NN + j0]);
    o0[0] = make_float2(sc0 * a00, sc0 * a01);
    o0[1] = make_float2(sc0 * a02, sc0 * a03);
    o1[0] = make_float2(sc1 * a10, sc1 * a11);
    o1[1] = make_float2(sc1 * a12, sc1 * a13);
}

// ---- kernel 4: transpose gcn_w --------------------------------------------
__global__ void k_transpose(const float* __restrict__ gw) {
    int idx = blockIdx.x * blockDim.x + threadIdx.x;
    if (idx < WOUT * XD) {
        int jj = idx / XD, kk = idx % XD;
        g_gwT[kk][jj] = gw[idx];
    }
}

// ---- kernel 5: classification head ----------------------------------------
__global__ void k_head(const float* __restrict__ Xm, const float* __restrict__ gcn_b,
                       const float* __restrict__ lin_w, const float* __restrict__ lin_b,
                       const int* __restrict__ tx, float* __restrict__ y) {
    int t = blockIdx.x;
    int row = tx[t];
    __shared__ float xr[XD];
    __shared__ float h[WOUT];
    for (int k = threadIdx.x; k < XD; k += blockDim.x)
        xr[k] = Xm[(size_t)row * XD + k];
    __syncthreads();
    int j = threadIdx.x;
    float acc = gcn_b[j];
    #pragma unroll 8
    for (int k = 0; k < XD; k++) acc += g_gwT[k][j] * xr[k];
    h[j] = fmaxf(acc, 0.f);
    __syncthreads();
    if (j < NCLS) {
        float acc2 = lin_b[j];
        #pragma unroll 4
        for (int m = 0; m < WOUT; m++)
            acc2 += (lin_w[j * (NC * WOUT) + m] + lin_w[j * (NC * WOUT) + WOUT + m]) * h[m];
        y[t * NCLS + j] = acc2;
    }
}

// ------------------------------ launch -------------------------------------
extern "C" void kernel_launch(void* const* d_in, const int* in_sizes, int n_in,
                              void* d_out, int out_size) {
    const float* A     = (const float*)d_in[0];
    const float* X     = (const float*)d_in[1];
    const float* w01   = (const float*)d_in[2];
    const float* w02   = (const float*)d_in[3];
    const float* w11   = (const float*)d_in[4];
    const float* gcn_w = (const float*)d_in[5];
    const float* gcn_b = (const float*)d_in[6];
    const float* lin_w = (const float*)d_in[7];
    const float* lin_b = (const float*)d_in[8];
    const int*   tx    = (const int*)d_in[9];
    float* out = (float*)d_out;

    k_fill<<<NN, 256>>>(A, w01, w02, w11, out + WS_OFF);
    k_M<<<NN, 256>>>();
    k_spmm<<<NN, 512>>>(out + H_OFF);
    k_transpose<<<(WOUT * XD + 255) / 256, 256>>>(gcn_w);
    k_head<<<NT, 128>>>(X, gcn_b, lin_w, lin_b, tx, out + Y_OFF);
}

// round 16
// speedup vs baseline: 2.2254x; 1.0012x over previous
#include <cuda_runtime.h>
#include <cuda_fp16.h>
#include <math.h>
#include <stdint.h>

// ---------------------------------------------------------------------------
// GTN: H = diag(s) * HA * (HB*HB2), union-sparse pattern, fp16 dense M.
// Round 16 = round-15 + tail-kernel absorption:
//  - gcn_w transpose runs as 64 extra blocks of k_fill (independent work)
//  - classification head runs as 512 extra blocks of k_spmm
//  -> pipeline: k_fill(+transpose) -> k_M -> k_spmm(+head). 3 launches total.
// Output: y[512*8] | all_Ws[3*2*5] | H[2*2048*2048]
// ---------------------------------------------------------------------------

#define NN    2048
#define NE    5
#define NC    2
#define CAP   256
#define NT    512
#define XD    512
#define WOUT  128
#define NCLS  8

#define Y_OFF  0
#define WS_OFF (NT * NCLS)
#define H_OFF  (WS_OFF + 3 * NC * NE)   // 4126 floats (8B aligned)

#define TR_BLOCKS 64                    // transpose blocks appended to k_fill

// ------------------------- static device scratch ---------------------------
__device__ int     g_cnt[NN];
__device__ int     g_cols[NN * CAP];
__device__ float   g_hav [NC][NN * CAP];
__device__ float   g_hbv [NC][NN * CAP];
__device__ __align__(16) int2 g_pb [NN * CAP];   // {col, HB packed half2 bits}
__device__ __align__(16) int2 g_pb2[NN * CAP];   // {col, HB2 packed half2 bits}
__device__ float   g_rB  [NC][NN];
__device__ float   g_rB2 [NC][NN];
__device__ float   g_rM  [NC][NN];
__device__ float   g_deg0[NC][NN];
__device__ __align__(16) __half2 g_Mi[NN][NN];   // M interleaved {c0,c1}, 16.8 MB
__device__ float   g_gwT[XD][WOUT];

// ------------------------------ helpers ------------------------------------
__device__ __forceinline__ float warpSum(float v) {
    #pragma unroll
    for (int o = 16; o > 0; o >>= 1) v += __shfl_down_sync(0xffffffffu, v, o);
    return v;
}
__device__ __forceinline__ __half2 bits2h2(int b) {
    __half2 h; *reinterpret_cast<int*>(&h) = b; return h;
}

// ---- kernel 1: pattern + values + rowsums + softmax + (transpose blocks) --
__global__ void k_fill(const float* __restrict__ A,
                       const float* __restrict__ w1, const float* __restrict__ w2,
                       const float* __restrict__ w3, float* __restrict__ out_ws,
                       const float* __restrict__ gw) {
    int i = blockIdx.x;
    int tid = threadIdx.x;
    // ---- absorbed transpose blocks (independent of fill work) ----
    if (i >= NN) {
        int tb = i - NN;
        #pragma unroll
        for (int r = 0; r < 4; r++) {
            int idx = tb * 1024 + r * 256 + tid;
            int jj = idx / XD, kk = idx % XD;
            g_gwT[kk][jj] = gw[idx];
        }
        return;
    }
    __shared__ float ssm[3][NC][NE];
    __shared__ float srb[NC], srb2[NC];
    __shared__ int scnt;
    if (tid == 0) scnt = 0;
    if (tid < NC) { srb[tid] = 0.f; srb2[tid] = 0.f; }
    if (tid < 3 * NC) {
        int m = tid / NC, c = tid % NC;
        const float* w = (m == 0 ? w1 : (m == 1 ? w2 : w3)) + c * NE;
        float mx = w[0];
        #pragma unroll
        for (int e = 1; e < NE; e++) mx = fmaxf(mx, w[e]);
        float ex[NE], s = 0.f;
        #pragma unroll
        for (int e = 0; e < NE; e++) { ex[e] = expf(w[e] - mx); s += ex[e]; }
        float inv = 1.f / s;
        #pragma unroll
        for (int e = 0; e < NE; e++) {
            float v = ex[e] * inv;
            ssm[m][c][e] = v;
            if (i == 0) out_ws[m * NC * NE + c * NE + e] = v;
        }
    }
    __syncthreads();
    float s1[NC][NE], s2[NC][NE], s3[NC][NE];
    #pragma unroll
    for (int c = 0; c < NC; c++)
        #pragma unroll
        for (int e = 0; e < NE; e++) {
            s1[c][e] = ssm[0][c][e]; s2[c][e] = ssm[1][c][e]; s3[c][e] = ssm[2][c][e];
        }
    for (int jb = tid * 4; jb < NN; jb += blockDim.x * 4) {
        float4 av[NE];
        #pragma unroll
        for (int e = 0; e < NE; e++)
            av[e] = *reinterpret_cast<const float4*>(
                A + (size_t)e * NN * NN + (size_t)i * NN + jb);
        #pragma unroll
        for (int q = 0; q < 4; q++) {
            float a[NE];
            a[0] = q == 0 ? av[0].x : q == 1 ? av[0].y : q == 2 ? av[0].z : av[0].w;
            a[1] = q == 0 ? av[1].x : q == 1 ? av[1].y : q == 2 ? av[1].z : av[1].w;
            a[2] = q == 0 ? av[2].x : q == 1 ? av[2].y : q == 2 ? av[2].z : av[2].w;
            a[3] = q == 0 ? av[3].x : q == 1 ? av[3].y : q == 2 ? av[3].z : av[3].w;
            a[4] = q == 0 ? av[4].x : q == 1 ? av[4].y : q == 2 ? av[4].z : av[4].w;
            bool nz = (a[0] != 0.f) | (a[1] != 0.f) | (a[2] != 0.f) |
                      (a[3] != 0.f) | (a[4] != 0.f);
            if (nz) {
                int slot = atomicAdd(&scnt, 1);
                if (slot < CAP) {
                    int p = i * CAP + slot;
                    int j = jb + q;
                    g_cols[p] = j;
                    float vb_[NC], vb2_[NC];
                    #pragma unroll
                    for (int c = 0; c < NC; c++) {
                        float va = 0.f, vb = 0.f, vb2 = 0.f;
                        #pragma unroll
                        for (int e = 0; e < NE; e++) {
                            va  += s1[c][e] * a[e];
                            vb  += s2[c][e] * a[e];
                            vb2 += s3[c][e] * a[e];
                        }
                        g_hav[c][p] = va; g_hbv[c][p] = vb;
                        vb_[c] = vb; vb2_[c] = vb2;
                        atomicAdd(&srb[c],  vb);
                        atomicAdd(&srb2[c], vb2);
                    }
                    __half2 hb  = __floats2half2_rn(vb_[0],  vb_[1]);
                    __half2 hb2 = __floats2half2_rn(vb2_[0], vb2_[1]);
                    g_pb [p] = make_int2(j, *reinterpret_cast<int*>(&hb));
                    g_pb2[p] = make_int2(j, *reinterpret_cast<int*>(&hb2));
                }
            }
        }
    }
    __syncthreads();
    if (tid < NC) { g_rB[tid][i] = srb[tid]; g_rB2[tid][i] = srb2[tid]; }
    if (tid == 0) {
        int cnt = min(scnt, CAP);
        g_cnt[i] = cnt;
        // pad to even for k_M's paired LDG.128 inner loop (zero no-op entry)
        if (cnt < CAP && (cnt & 1)) g_pb2[i * CAP + cnt] = make_int2(0, 0);
    }
}

// ---- kernel 2: M = HB @ HB2 + per-row deg0/rM (k_deg folded in) -----------
__global__ void k_M() {
    int k = blockIdx.x;
    __shared__ __align__(16) __half2 acc[NN];         // 8 KB, {c0,c1} per col
    __shared__ int  sl[CAP];
    __shared__ int  shb[CAP];
    __shared__ int  snp[CAP];
    __shared__ float sred[8][4];
    for (int j = threadIdx.x; j < NN; j += blockDim.x)
        acc[j] = __float2half2_rn(0.f);
    int cnt = g_cnt[k];
    int tid = threadIdx.x;
    float d0 = 0.f, d1 = 0.f, m0 = 0.f, m1 = 0.f;
    if (tid < cnt) {
        int p = k * CAP + tid;
        int2 pe = g_pb[p];
        sl[tid]  = pe.x;
        shb[tid] = pe.y;
        snp[tid] = (g_cnt[pe.x] + 1) >> 1;
        int col = pe.x;
        d0 = g_hav[0][p] * g_rB[0][col];
        d1 = g_hav[1][p] * g_rB[1][col];
        m0 = g_hbv[0][p] * g_rB2[0][col];
        m1 = g_hbv[1][p] * g_rB2[1][col];
    }
    d0 = warpSum(d0); d1 = warpSum(d1); m0 = warpSum(m0); m1 = warpSum(m1);
    int warp = tid >> 5, lane = tid & 31;
    if (lane == 0) { sred[warp][0] = d0; sred[warp][1] = d1; sred[warp][2] = m0; sred[warp][3] = m1; }
    __syncthreads();
    if (tid == 0) {
        float v0 = 0, v1 = 0, v2 = 0, v3 = 0;
        #pragma unroll
        for (int q = 0; q < 8; q++) { v0 += sred[q][0]; v1 += sred[q][1]; v2 += sred[q][2]; v3 += sred[q][3]; }
        g_deg0[0][k] = v0; g_deg0[1][k] = v1; g_rM[0][k] = v2; g_rM[1][k] = v3;
    }
    for (int pi = warp; pi < cnt; pi += 8) {
        int l = sl[pi];
        __half2 hb = bits2h2(shb[pi]);
        int npairs = snp[pi];
        const int4* src = reinterpret_cast<const int4*>(&g_pb2[l * CAP]);
        for (int t = lane; t < npairs; t += 32) {
            int4 qq = src[t];                         // 2 entries, 1 LDG.128
            atomicAdd(&acc[qq.x], __hmul2(hb, bits2h2(qq.y)));
            atomicAdd(&acc[qq.z], __hmul2(hb, bits2h2(qq.w)));
        }
    }
    __syncthreads();
    uint4* dst = reinterpret_cast<uint4*>(&g_Mi[k][0]);
    const uint4* s4 = reinterpret_cast<const uint4*>(acc);
    for (int t = threadIdx.x; t < NN / 4; t += blockDim.x)
        dst[t] = s4[t];
}

// ---- kernel 3: H = diag(scale)*HA@M  (+ absorbed head blocks) -------------
__global__ void __launch_bounds__(512) k_spmm(float* __restrict__ H,
        const float* __restrict__ Xm, const float* __restrict__ gcn_b,
        const float* __restrict__ lin_w, const float* __restrict__ lin_b,
        const int* __restrict__ tx, float* __restrict__ y) {
    const int i = blockIdx.x;
    const int tid = threadIdx.x;
    // ---- absorbed classification-head blocks ----
    if (i >= NN) {
        int t = i - NN;
        int row = tx[t];
        __shared__ float xr[XD];
        __shared__ float h[WOUT];
        for (int k = tid; k < XD; k += blockDim.x)
            xr[k] = Xm[(size_t)row * XD + k];
        __syncthreads();
        if (tid < WOUT) {
            float acc = gcn_b[tid];
            #pragma unroll 8
            for (int k = 0; k < XD; k++) acc += g_gwT[k][tid] * xr[k];
            h[tid] = fmaxf(acc, 0.f);
        }
        __syncthreads();
        if (tid < NCLS) {
            float acc2 = lin_b[tid];
            #pragma unroll 4
            for (int m = 0; m < WOUT; m++)
                acc2 += (lin_w[tid * (NC * WOUT) + m] + lin_w[tid * (NC * WOUT) + WOUT + m]) * h[m];
            y[t * NCLS + tid] = acc2;
        }
        return;
    }
    const int j0 = tid * 4;
    __shared__ int    scol[CAP];
    __shared__ float2 sw[CAP];
    __shared__ float sred[16][2];
    __shared__ float ssc[2];
    const int cnt = g_cnt[i];
    float t0 = 0.f, t1 = 0.f;
    if (tid < cnt) {
        int p = i * CAP + tid;
        int col = g_cols[p];
        float2 wv = make_float2(g_hav[0][p], g_hav[1][p]);
        scol[tid] = col;
        sw[tid]   = wv;
        t0 = wv.x * g_rM[0][col];
        t1 = wv.y * g_rM[1][col];
    }
    t0 = warpSum(t0); t1 = warpSum(t1);
    const int warp = tid >> 5, lane = tid & 31;
    if (lane == 0) { sred[warp][0] = t0; sred[warp][1] = t1; }
    __syncthreads();
    if (tid == 0) {
        float tt0 = 0, tt1 = 0;
        #pragma unroll
        for (int q = 0; q < 16; q++) { tt0 += sred[q][0]; tt1 += sred[q][1]; }
        float dg0 = g_deg0[0][i];
        float d0 = (dg0 > 0.f) ? (1.f / sqrtf(dg0)) : 0.f;
        float dg1 = d0 * tt0;
        float d1 = (dg1 > 0.f) ? (1.f / sqrtf(dg1)) : 0.f;
        ssc[0] = d0 * d1;
        dg0 = g_deg0[1][i];
        d0 = (dg0 > 0.f) ? (1.f / sqrtf(dg0)) : 0.f;
        dg1 = d0 * tt1;
        d1 = (dg1 > 0.f) ? (1.f / sqrtf(dg1)) : 0.f;
        ssc[1] = d0 * d1;
    }
    __syncthreads();
    float a00 = 0, a01 = 0, a02 = 0, a03 = 0;   // channel 0
    float a10 = 0, a11 = 0, a12 = 0, a13 = 0;   // channel 1
    #define ACCUM(mv, wv) do {                                    \
        float2 f0 = __half22float2(bits2h2((int)(mv).x));         \
        float2 f1 = __half22float2(bits2h2((int)(mv).y));         \
        float2 f2 = __half22float2(bits2h2((int)(mv).z));         \
        float2 f3 = __half22float2(bits2h2((int)(mv).w));         \
        a00 += (wv).x * f0.x; a10 += (wv).y * f0.y;               \
        a01 += (wv).x * f1.x; a11 += (wv).y * f1.y;               \
        a02 += (wv).x * f2.x; a12 += (wv).y * f2.y;               \
        a03 += (wv).x * f3.x; a13 += (wv).y * f3.y;               \
    } while (0)
    int l = 0;
    for (; l + 8 <= cnt; l += 8) {
        uint4 m0 = *reinterpret_cast<const uint4*>(&g_Mi[scol[l + 0]][j0]);
        uint4 m1 = *reinterpret_cast<const uint4*>(&g_Mi[scol[l + 1]][j0]);
        uint4 m2 = *reinterpret_cast<const uint4*>(&g_Mi[scol[l + 2]][j0]);
        uint4 m3 = *reinterpret_cast<const uint4*>(&g_Mi[scol[l + 3]][j0]);
        uint4 m4 = *reinterpret_cast<const uint4*>(&g_Mi[scol[l + 4]][j0]);
        uint4 m5 = *reinterpret_cast<const uint4*>(&g_Mi[scol[l + 5]][j0]);
        uint4 m6 = *reinterpret_cast<const uint4*>(&g_Mi[scol[l + 6]][j0]);
        uint4 m7 = *reinterpret_cast<const uint4*>(&g_Mi[scol[l + 7]][j0]);
        float2 w0 = sw[l + 0], w1 = sw[l + 1], w2 = sw[l + 2], w3 = sw[l + 3];
        float2 w4 = sw[l + 4], w5 = sw[l + 5], w6 = sw[l + 6], w7 = sw[l + 7];
        ACCUM(m0, w0); ACCUM(m1, w1); ACCUM(m2, w2); ACCUM(m3, w3);
        ACCUM(m4, w4); ACCUM(m5, w5); ACCUM(m6, w6); ACCUM(m7, w7);
    }
    for (; l < cnt; l++) {
        uint4 m0 = *reinterpret_cast<const uint4*>(&g_Mi[scol[l]][j0]);
        float2 w0 = sw[l];
        ACCUM(m0, w0);
    }
    #undef ACCUM
    const float sc0 = ssc[0];
    const float sc1 = ssc[1];
    float2* o0 = reinterpret_cast<float2*>(&H[(size_t)0 * NN * NN + (size_t)i * NN + j0]);
    float2* o1 = reinterpret_cast<float2*>(&H[(size_t)1 * NN * NN + (size_t)i * NN + j0]);
    o0[0] = make_float2(sc0 * a00, sc0 * a01);
    o0[1] = make_float2(sc0 * a02, sc0 * a03);
    o1[0] = make_float2(sc1 * a10, sc1 * a11);
    o1[1] = make_float2(sc1 * a12, sc1 * a13);
}

// ------------------------------ launch -------------------------------------
extern "C" void kernel_launch(void* const* d_in, const int* in_sizes, int n_in,
                              void* d_out, int out_size) {
    const float* A     = (const float*)d_in[0];
    const float* X     = (const float*)d_in[1];
    const float* w01   = (const float*)d_in[2];
    const float* w02   = (const float*)d_in[3];
    const float* w11   = (const float*)d_in[4];
    const float* gcn_w = (const float*)d_in[5];
    const float* gcn_b = (const float*)d_in[6];
    const float* lin_w = (const float*)d_in[7];
    const float* lin_b = (const float*)d_in[8];
    const int*   tx    = (const int*)d_in[9];
    float* out = (float*)d_out;

    k_fill<<<NN + TR_BLOCKS, 256>>>(A, w01, w02, w11, out + WS_OFF, gcn_w);
    k_M<<<NN, 256>>>();
    k_spmm<<<NN + NT, 512>>>(out + H_OFF, X, gcn_b, lin_w, lin_b, tx, out + Y_OFF);
}